// round 5
// baseline (speedup 1.0000x reference)
#include <cuda_runtime.h>
#include <cuda_bf16.h>
#include <cstdint>
#include <math.h>

#define B_   8
#define N_   4096
#define K_   32
#define C_   128
#define O_   64
#define NH_  80
#define TN_  8
#define M2_  256            // positions per block

// ---- smem layout (bytes) ----
#define SM_W    0           // 40960: hi at 0, lo at +20480
#define SM_XB   40960       // 2 bufs x 16384 (hi 8192 + lo 8192): 16c x 256m bf16
#define SM_WF   82944       // 256 floats (placed above Ys overlay)
#define SM_OBUF 83968       // 64 x 9 floats = 2304
#define SM_TOTAL 86272
#define SM_YS   0           // overlay (after last MMA): 256 x 81 floats = 82944B
#define YS_STRIDE 81        // 80 used cols + pad (R4 bug: was 65 -> row aliasing)

__device__ __forceinline__ uint32_t smem_u32(const void* p) {
    uint32_t a;
    asm("{ .reg .u64 t; cvta.to.shared.u64 t, %1; cvt.u32.u64 %0, t; }" : "=r"(a) : "l"(p));
    return a;
}

#define LDSM_X4(r, a) \
    asm volatile("ldmatrix.sync.aligned.m8n8.x4.shared.b16 {%0,%1,%2,%3}, [%4];" \
        : "=r"((r)[0]), "=r"((r)[1]), "=r"((r)[2]), "=r"((r)[3]) : "r"(a))
#define LDSM_X4_T(r, a) \
    asm volatile("ldmatrix.sync.aligned.m8n8.x4.trans.shared.b16 {%0,%1,%2,%3}, [%4];" \
        : "=r"((r)[0]), "=r"((r)[1]), "=r"((r)[2]), "=r"((r)[3]) : "r"(a))
#define MMA_BF16(c, a, b0, b1) \
    asm volatile("mma.sync.aligned.m16n8k16.row.col.f32.bf16.bf16.f32 " \
        "{%0,%1,%2,%3},{%4,%5,%6,%7},{%8,%9},{%0,%1,%2,%3};" \
        : "+f"((c)[0]), "+f"((c)[1]), "+f"((c)[2]), "+f"((c)[3]) \
        : "r"((a)[0]), "r"((a)[1]), "r"((a)[2]), "r"((a)[3]), "r"(b0), "r"(b1))

__device__ __forceinline__ uint32_t pack_bf2(float a, float b) {
    __nv_bfloat162 h = __floats2bfloat162_rn(a, b);
    return *reinterpret_cast<uint32_t*>(&h);
}

// ================= weight prep (same proven image as R3) =================
// byte(o,c) = o*256 + (((c>>3) ^ (o&7)) << 4) + (c&7)*2 ; hi plane then lo at +20480
__device__ uint4 g_Wimg[2560];

__global__ void prep_b(const float* __restrict__ wt, const float* __restrict__ wg,
                       const float* __restrict__ wa) {
    int i = blockIdx.x * blockDim.x + threadIdx.x;
    if (i >= NH_ * C_) return;
    int o = i >> 7, c = i & 127;
    float w = (o < 64) ? wt[o * C_ + c]
            : (o < 72) ? wg[(o - 64) * C_ + c]
                       : wa[(o - 72) * C_ + c];
    __nv_bfloat16 h = __float2bfloat16(w);
    __nv_bfloat16 l = __float2bfloat16(w - __bfloat162float(h));
    unsigned byte = (unsigned)o * 256u + ((((unsigned)(c >> 3) ^ (o & 7)) << 4)) + (c & 7) * 2u;
    __nv_bfloat16* base = (__nv_bfloat16*)g_Wimg;
    base[byte >> 1] = h;
    base[(20480u + byte) >> 1] = l;
}

// ================= main kernel =================
__global__ __launch_bounds__(256)
void gsl_mma(const float* __restrict__ x,
             const float* __restrict__ g_trans, const float* __restrict__ b_trans,
             const float* __restrict__ g_gate,  const float* __restrict__ b_gate,
             const float* __restrict__ w_gate2, const float* __restrict__ b_gate2,
             const float* __restrict__ g_attn,  const float* __restrict__ b_attn,
             const float* __restrict__ w_attn2, const float* __restrict__ b_attn2,
             const float* __restrict__ agg_alpha,
             float* __restrict__ out, float* __restrict__ gate_out)
{
    extern __shared__ char smem[];
    const uint32_t sb = smem_u32(smem);
    const int t    = threadIdx.x;
    const int wid  = t >> 5;
    const int lane = t & 31;
    const int blk  = blockIdx.x;
    const int b    = blk >> 9;
    const int nb   = (blk & 511) * TN_;

    // ---- copy weight images (40960 B) ----
    {
        uint4* d = (uint4*)smem;
        #pragma unroll
        for (int i = 0; i < 10; i++) d[t + 256 * i] = g_Wimg[t + 256 * i];
    }

    const int xbase = b * (C_ * N_ * K_) + nb * K_;
    const int crow  = t >> 6;          // c row (mod 4) handled by this thread
    const int q     = t & 63;          // float4 index within 256m row

    // ---- prologue: LDG chunk 0 + STS to buf 0 ----
    float4 stg[4];
    #pragma unroll
    for (int it = 0; it < 4; it++) {
        int c = crow + it * 4;
        stg[it] = *(const float4*)(x + xbase + c * (N_ * K_) + q * 4);
    }
    {
        char* Xhi = smem + SM_XB;
        #pragma unroll
        for (int it = 0; it < 4; it++) {
            int c = crow + it * 4;
            float4 v = stg[it];
            __nv_bfloat16 h0 = __float2bfloat16(v.x), h1 = __float2bfloat16(v.y);
            __nv_bfloat16 h2 = __float2bfloat16(v.z), h3 = __float2bfloat16(v.w);
            uint2 ph, pl;
            ph.x = (uint32_t)__bfloat16_as_ushort(h0) | ((uint32_t)__bfloat16_as_ushort(h1) << 16);
            ph.y = (uint32_t)__bfloat16_as_ushort(h2) | ((uint32_t)__bfloat16_as_ushort(h3) << 16);
            pl.x = pack_bf2(v.x - __bfloat162float(h0), v.y - __bfloat162float(h1));
            pl.y = pack_bf2(v.z - __bfloat162float(h2), v.w - __bfloat162float(h3));
            unsigned off = (unsigned)c * 512u + ((((unsigned)(q >> 1)) ^ (c & 7)) << 4) + (q & 1) * 8u;
            *(uint2*)(Xhi + off) = ph;
            *(uint2*)(Xhi + 8192 + off) = pl;
        }
    }
    __syncthreads();

    // ---- fragment addressing ----
    const int l7   = lane & 7;
    const int koff = (lane >> 3) & 1;
    const int r16  = l7 + ((lane & 16) >> 1);
    uint32_t aBase[2];
    #pragma unroll
    for (int mt = 0; mt < 2; mt++)
        aBase[mt] = sb + SM_XB + r16 * 512 + ((((unsigned)(4 * wid + 2 * mt + koff)) ^ l7) << 4);
    const uint32_t bRowHi = sb + SM_W + r16 * 256;

    float acc[2][10][4];
    #pragma unroll
    for (int mt = 0; mt < 2; mt++)
        #pragma unroll
        for (int i = 0; i < 10; i++)
            #pragma unroll
            for (int j = 0; j < 4; j++) acc[mt][i][j] = 0.0f;

    // ---- pipelined mainloop over 8 k-steps (16 c each) ----
    #pragma unroll 2
    for (int s = 0; s < 8; s++) {
        if (s < 7) {
            #pragma unroll
            for (int it = 0; it < 4; it++) {
                int c = 16 * (s + 1) + crow + it * 4;
                stg[it] = *(const float4*)(x + xbase + c * (N_ * K_) + q * 4);
            }
        }
        const uint32_t xb = (uint32_t)(s & 1) * 16384u;
        uint32_t ah[2][4], al[2][4];
        #pragma unroll
        for (int mt = 0; mt < 2; mt++) {
            LDSM_X4_T(ah[mt], aBase[mt] + xb);
            LDSM_X4_T(al[mt], aBase[mt] + xb + 8192);
        }
        const uint32_t cs = ((((unsigned)(2 * s + koff)) ^ l7) << 4);
        #pragma unroll
        for (int jp = 0; jp < 5; jp++) {
            uint32_t bh[4], bl[4];
            LDSM_X4(bh, bRowHi + jp * 4096 + cs);
            LDSM_X4(bl, bRowHi + 20480 + jp * 4096 + cs);
            #pragma unroll
            for (int mt = 0; mt < 2; mt++) {
                MMA_BF16(acc[mt][2 * jp],     ah[mt], bh[0], bh[1]);
                MMA_BF16(acc[mt][2 * jp + 1], ah[mt], bh[2], bh[3]);
                MMA_BF16(acc[mt][2 * jp],     al[mt], bh[0], bh[1]);
                MMA_BF16(acc[mt][2 * jp + 1], al[mt], bh[2], bh[3]);
                MMA_BF16(acc[mt][2 * jp],     ah[mt], bl[0], bl[1]);
                MMA_BF16(acc[mt][2 * jp + 1], ah[mt], bl[2], bl[3]);
            }
        }
        if (s < 7) {
            char* Xhi = smem + SM_XB + (((s + 1) & 1) ? 16384 : 0);
            #pragma unroll
            for (int it = 0; it < 4; it++) {
                int c = crow + it * 4;   // local row within chunk
                float4 v = stg[it];
                __nv_bfloat16 h0 = __float2bfloat16(v.x), h1 = __float2bfloat16(v.y);
                __nv_bfloat16 h2 = __float2bfloat16(v.z), h3 = __float2bfloat16(v.w);
                uint2 ph, pl;
                ph.x = (uint32_t)__bfloat16_as_ushort(h0) | ((uint32_t)__bfloat16_as_ushort(h1) << 16);
                ph.y = (uint32_t)__bfloat16_as_ushort(h2) | ((uint32_t)__bfloat16_as_ushort(h3) << 16);
                pl.x = pack_bf2(v.x - __bfloat162float(h0), v.y - __bfloat162float(h1));
                pl.y = pack_bf2(v.z - __bfloat162float(h2), v.w - __bfloat162float(h3));
                unsigned off = (unsigned)c * 512u + ((((unsigned)(q >> 1)) ^ (c & 7)) << 4) + (q & 1) * 8u;
                *(uint2*)(Xhi + off) = ph;
                *(uint2*)(Xhi + 8192 + off) = pl;
            }
        }
        __syncthreads();
    }

    // ---- scatter accumulators to Ys[m][o] (overlays W + Xbuf, safe post-sync) ----
    float* Ys = (float*)(smem + SM_YS);
    {
        const int m0  = 32 * wid + (lane >> 2);
        const int nb4 = 2 * (lane & 3);
        #pragma unroll
        for (int mt = 0; mt < 2; mt++) {
            const int mr = m0 + 16 * mt;
            #pragma unroll
            for (int jj = 0; jj < 10; jj++) {
                const int n0 = 8 * jj + nb4;
                Ys[mr * YS_STRIDE + n0]           = acc[mt][jj][0];
                Ys[mr * YS_STRIDE + n0 + 1]       = acc[mt][jj][1];
                Ys[(mr + 8) * YS_STRIDE + n0]     = acc[mt][jj][2];
                Ys[(mr + 8) * YS_STRIDE + n0 + 1] = acc[mt][jj][3];
            }
        }
    }
    __syncthreads();

    // ---- phase A+B: heads + masked softmax (warp = n-row, lane = k), m = t ----
    float* WF = (float*)(smem + SM_WF);
    {
        const int m = t;
        float gl = b_gate2[0];
        float al = b_attn2[0];
        #pragma unroll
        for (int h = 0; h < 8; h++) {
            float yg = Ys[m * YS_STRIDE + 64 + h];
            float v  = fmaf(g_gate[h], yg, b_gate[h]);
            v = (v >= 0.0f) ? v : 0.2f * v;
            gl = fmaf(w_gate2[h], v, gl);
            float ya = Ys[m * YS_STRIDE + 72 + h];
            float u  = fmaf(g_attn[h], ya, b_attn[h]);
            u = (u >= 0.0f) ? u : 0.2f * u;
            al = fmaf(w_attn2[h], u, al);
        }
        gate_out[b * (N_ * K_) + nb * K_ + m] = gl;

        float amax = al;
        #pragma unroll
        for (int s = 16; s > 0; s >>= 1)
            amax = fmaxf(amax, __shfl_xor_sync(0xffffffffu, amax, s));
        float e = __expf(al - amax);
        float S = e;
        #pragma unroll
        for (int s = 16; s > 0; s >>= 1)
            S += __shfl_xor_sync(0xffffffffu, S, s);
        float w  = e / S;
        float wm = (gl >= 0.0f) ? w : 0.0f;
        float Sm = wm;
        #pragma unroll
        for (int s = 16; s > 0; s >>= 1)
            Sm += __shfl_xor_sync(0xffffffffu, Sm, s);
        WF[m] = wm / (Sm + 1e-6f);
    }
    __syncthreads();

    // ---- phase C: affine + lrelu, weighted sum + max over k (2 n-rows/thread) ----
    const float alpha = 1.0f / (1.0f + __expf(-agg_alpha[0]));
    float* Obuf = (float*)(smem + SM_OBUF);
    {
        const int o = t & 63;
        const float g  = g_trans[o];
        const float bb = b_trans[o];
        #pragma unroll
        for (int half = 0; half < 2; half++) {
            const int nn = (t >> 6) + 4 * half;
            const int mBase = nn * K_;
            float s  = 0.0f;
            float mx = -INFINITY;
            #pragma unroll
            for (int k = 0; k < K_; k++) {
                float y  = Ys[(mBase + k) * YS_STRIDE + o];
                float tv = fmaf(g, y, bb);
                tv = (tv >= 0.0f) ? tv : 0.2f * tv;
                s  = fmaf(tv, WF[mBase + k], s);
                mx = fmaxf(mx, tv);
            }
            Obuf[o * 9 + nn] = alpha * s + (1.0f - alpha) * mx;
        }
    }
    __syncthreads();

    if (t < 128) {
        const int o = t >> 1, h = t & 1;
        float4 v;
        v.x = Obuf[o * 9 + 4 * h];
        v.y = Obuf[o * 9 + 4 * h + 1];
        v.z = Obuf[o * 9 + 4 * h + 2];
        v.w = Obuf[o * 9 + 4 * h + 3];
        *(float4*)(out + (b * O_ + o) * N_ + nb + 4 * h) = v;
    }
}

extern "C" void kernel_launch(void* const* d_in, const int* in_sizes, int n_in,
                              void* d_out, int out_size) {
    const float* x        = (const float*)d_in[0];
    const float* w_trans  = (const float*)d_in[1];
    const float* g_trans  = (const float*)d_in[2];
    const float* b_trans  = (const float*)d_in[3];
    const float* w_gate1  = (const float*)d_in[4];
    const float* g_gate   = (const float*)d_in[5];
    const float* b_gate   = (const float*)d_in[6];
    const float* w_gate2  = (const float*)d_in[7];
    const float* b_gate2  = (const float*)d_in[8];
    const float* w_attn1  = (const float*)d_in[9];
    const float* g_attn   = (const float*)d_in[10];
    const float* b_attn   = (const float*)d_in[11];
    const float* w_attn2  = (const float*)d_in[12];
    const float* b_attn2  = (const float*)d_in[13];
    const float* agg_alpha= (const float*)d_in[14];

    float* out      = (float*)d_out;                  // [B,O,N]
    float* gate_out = out + (size_t)B_ * O_ * N_;     // [B,1,N,K]

    cudaFuncSetAttribute(gsl_mma, cudaFuncAttributeMaxDynamicSharedMemorySize, SM_TOTAL);

    prep_b<<<(NH_ * C_ + 255) / 256, 256>>>(w_trans, w_gate1, w_attn1);
    gsl_mma<<<B_ * (N_ / TN_), 256, SM_TOTAL>>>(
        x, g_trans, b_trans, g_gate, b_gate, w_gate2, b_gate2,
        g_attn, b_attn, w_attn2, b_attn2, agg_alpha, out, gate_out);
}

// round 6
// speedup vs baseline: 1.1343x; 1.1343x over previous
#include <cuda_runtime.h>
#include <cuda_bf16.h>
#include <cstdint>
#include <math.h>

#define B_   8
#define N_   4096
#define K_   32
#define C_   128
#define O_   64
#define NH_  80
#define TN_  8
#define M2_  256            // positions per block

// ---- smem layout (bytes) ----
#define SM_W    0           // 40960: W hi at 0, lo at +20480
#define SM_XB   40960       // 2 bufs x 32768: 32c x 256m bf16 (hi 16384 + lo 16384)
#define SM_WF   106496      // 256 floats
#define SM_OBUF 107520      // 64 x 9 floats = 2304
#define SM_TOTAL 109824
#define SM_YS   0           // overlay (after last MMA): 256 x 81 floats = 82944B
#define YS_STRIDE 81

__device__ __forceinline__ uint32_t smem_u32(const void* p) {
    uint32_t a;
    asm("{ .reg .u64 t; cvta.to.shared.u64 t, %1; cvt.u32.u64 %0, t; }" : "=r"(a) : "l"(p));
    return a;
}

#define LDSM_X4(r, a) \
    asm volatile("ldmatrix.sync.aligned.m8n8.x4.shared.b16 {%0,%1,%2,%3}, [%4];" \
        : "=r"((r)[0]), "=r"((r)[1]), "=r"((r)[2]), "=r"((r)[3]) : "r"(a))
#define LDSM_X4_T(r, a) \
    asm volatile("ldmatrix.sync.aligned.m8n8.x4.trans.shared.b16 {%0,%1,%2,%3}, [%4];" \
        : "=r"((r)[0]), "=r"((r)[1]), "=r"((r)[2]), "=r"((r)[3]) : "r"(a))
#define MMA_BF16(c, a, b0, b1) \
    asm volatile("mma.sync.aligned.m16n8k16.row.col.f32.bf16.bf16.f32 " \
        "{%0,%1,%2,%3},{%4,%5,%6,%7},{%8,%9},{%0,%1,%2,%3};" \
        : "+f"((c)[0]), "+f"((c)[1]), "+f"((c)[2]), "+f"((c)[3]) \
        : "r"((a)[0]), "r"((a)[1]), "r"((a)[2]), "r"((a)[3]), "r"(b0), "r"(b1))

__device__ __forceinline__ uint32_t pack_bf2(float a, float b) {
    __nv_bfloat162 h = __floats2bfloat162_rn(a, b);
    return *reinterpret_cast<uint32_t*>(&h);
}

// ================= weight prep (proven R3 image) =================
// byte(o,c) = o*256 + (((c>>3) ^ (o&7)) << 4) + (c&7)*2 ; hi plane, lo at +20480
__device__ uint4 g_Wimg[2560];

__global__ void prep_b(const float* __restrict__ wt, const float* __restrict__ wg,
                       const float* __restrict__ wa) {
    int i = blockIdx.x * blockDim.x + threadIdx.x;
    if (i >= NH_ * C_) return;
    int o = i >> 7, c = i & 127;
    float w = (o < 64) ? wt[o * C_ + c]
            : (o < 72) ? wg[(o - 64) * C_ + c]
                       : wa[(o - 72) * C_ + c];
    __nv_bfloat16 h = __float2bfloat16(w);
    __nv_bfloat16 l = __float2bfloat16(w - __bfloat162float(h));
    unsigned byte = (unsigned)o * 256u + ((((unsigned)(c >> 3) ^ (o & 7)) << 4)) + (c & 7) * 2u;
    __nv_bfloat16* base = (__nv_bfloat16*)g_Wimg;
    base[byte >> 1] = h;
    base[(20480u + byte) >> 1] = l;
}

// STS one 32c chunk (hi+lo planes), converting fp32 -> bf16 Dekker split
__device__ __forceinline__ void sts_chunk(char* base, const float4* stg, int crow, int q) {
    #pragma unroll
    for (int it = 0; it < 8; it++) {
        int c = crow + it * 4;
        float4 v = stg[it];
        __nv_bfloat16 h0 = __float2bfloat16(v.x), h1 = __float2bfloat16(v.y);
        __nv_bfloat16 h2 = __float2bfloat16(v.z), h3 = __float2bfloat16(v.w);
        uint2 ph, pl;
        ph.x = (uint32_t)__bfloat16_as_ushort(h0) | ((uint32_t)__bfloat16_as_ushort(h1) << 16);
        ph.y = (uint32_t)__bfloat16_as_ushort(h2) | ((uint32_t)__bfloat16_as_ushort(h3) << 16);
        pl.x = pack_bf2(v.x - __bfloat162float(h0), v.y - __bfloat162float(h1));
        pl.y = pack_bf2(v.z - __bfloat162float(h2), v.w - __bfloat162float(h3));
        unsigned off = (unsigned)c * 512u + ((((unsigned)(q >> 1)) ^ (c & 7)) << 4) + (q & 1) * 8u;
        *(uint2*)(base + off) = ph;
        *(uint2*)(base + 16384 + off) = pl;
    }
}

// ================= main kernel =================
__global__ __launch_bounds__(256, 1)
void gsl_mma(const float* __restrict__ x,
             const float* __restrict__ g_trans, const float* __restrict__ b_trans,
             const float* __restrict__ g_gate,  const float* __restrict__ b_gate,
             const float* __restrict__ w_gate2, const float* __restrict__ b_gate2,
             const float* __restrict__ g_attn,  const float* __restrict__ b_attn,
             const float* __restrict__ w_attn2, const float* __restrict__ b_attn2,
             const float* __restrict__ agg_alpha,
             float* __restrict__ out, float* __restrict__ gate_out)
{
    extern __shared__ char smem[];
    const uint32_t sb = smem_u32(smem);
    const int t    = threadIdx.x;
    const int wid  = t >> 5;
    const int lane = t & 31;
    const int blk  = blockIdx.x;
    const int b    = blk >> 9;
    const int nb   = (blk & 511) * TN_;

    const int xbase = b * (C_ * N_ * K_) + nb * K_;
    const int crow  = t >> 6;          // c row (mod 4)
    const int q     = t & 63;          // float4 index within 256m row

    // ---- prologue: issue ALL LDGs (weights + chunk 0) before any STS ----
    uint4 wstg[10];
    {
        #pragma unroll
        for (int i = 0; i < 10; i++) wstg[i] = g_Wimg[t + 256 * i];
    }
    float4 stg[8];
    #pragma unroll
    for (int it = 0; it < 8; it++) {
        int c = crow + it * 4;
        stg[it] = *(const float4*)(x + xbase + c * (N_ * K_) + q * 4);
    }
    {
        uint4* d = (uint4*)smem;
        #pragma unroll
        for (int i = 0; i < 10; i++) d[t + 256 * i] = wstg[i];
    }
    sts_chunk(smem + SM_XB, stg, crow, q);
    __syncthreads();

    // ---- fragment addressing ----
    const int l7   = lane & 7;
    const int koff = (lane >> 3) & 1;
    const int r16  = l7 + ((lane & 16) >> 1);
    uint32_t aBase[2];
    #pragma unroll
    for (int mt = 0; mt < 2; mt++)
        aBase[mt] = sb + SM_XB + r16 * 512 + ((((unsigned)(4 * wid + 2 * mt + koff)) ^ l7) << 4);
    const uint32_t bRowHi = sb + SM_W + r16 * 256;

    float acc[2][10][4];
    #pragma unroll
    for (int mt = 0; mt < 2; mt++)
        #pragma unroll
        for (int i = 0; i < 10; i++)
            #pragma unroll
            for (int j = 0; j < 4; j++) acc[mt][i][j] = 0.0f;

    // ---- pipelined mainloop: 4 steps of 32 c ----
    #pragma unroll
    for (int s = 0; s < 4; s++) {
        if (s < 3) {
            #pragma unroll
            for (int it = 0; it < 8; it++) {
                int c = 32 * (s + 1) + crow + it * 4;
                stg[it] = *(const float4*)(x + xbase + c * (N_ * K_) + q * 4);
            }
        }
        const uint32_t xb = (uint32_t)(s & 1) * 32768u;
        #pragma unroll
        for (int g = 0; g < 2; g++) {
            uint32_t ah[2][4], al[2][4];
            #pragma unroll
            for (int mt = 0; mt < 2; mt++) {
                LDSM_X4_T(ah[mt], aBase[mt] + xb + g * 8192u);
                LDSM_X4_T(al[mt], aBase[mt] + xb + g * 8192u + 16384u);
            }
            const int st16 = 2 * s + g;
            const uint32_t cs = ((((unsigned)(2 * st16 + koff)) ^ l7) << 4);
            #pragma unroll
            for (int jp = 0; jp < 5; jp++) {
                uint32_t bh[4], bl[4];
                LDSM_X4(bh, bRowHi + jp * 4096 + cs);
                LDSM_X4(bl, bRowHi + 20480 + jp * 4096 + cs);
                #pragma unroll
                for (int mt = 0; mt < 2; mt++) {
                    MMA_BF16(acc[mt][2 * jp],     ah[mt], bh[0], bh[1]);
                    MMA_BF16(acc[mt][2 * jp + 1], ah[mt], bh[2], bh[3]);
                    MMA_BF16(acc[mt][2 * jp],     al[mt], bh[0], bh[1]);
                    MMA_BF16(acc[mt][2 * jp + 1], al[mt], bh[2], bh[3]);
                    MMA_BF16(acc[mt][2 * jp],     ah[mt], bl[0], bl[1]);
                    MMA_BF16(acc[mt][2 * jp + 1], ah[mt], bl[2], bl[3]);
                }
            }
        }
        if (s < 3)
            sts_chunk(smem + SM_XB + (((s + 1) & 1) ? 32768 : 0), stg, crow, q);
        __syncthreads();
    }

    // ---- scatter accumulators to Ys[m][o] (overlay, safe post-sync) ----
    float* Ys = (float*)(smem + SM_YS);
    {
        const int m0  = 32 * wid + (lane >> 2);
        const int nb4 = 2 * (lane & 3);
        #pragma unroll
        for (int mt = 0; mt < 2; mt++) {
            const int mr = m0 + 16 * mt;
            #pragma unroll
            for (int jj = 0; jj < 10; jj++) {
                const int n0 = 8 * jj + nb4;
                Ys[mr * YS_STRIDE + n0]           = acc[mt][jj][0];
                Ys[mr * YS_STRIDE + n0 + 1]       = acc[mt][jj][1];
                Ys[(mr + 8) * YS_STRIDE + n0]     = acc[mt][jj][2];
                Ys[(mr + 8) * YS_STRIDE + n0 + 1] = acc[mt][jj][3];
            }
        }
    }
    __syncthreads();

    // ---- phase A+B: heads + masked softmax (warp = n-row, lane = k), m = t ----
    float* WF = (float*)(smem + SM_WF);
    {
        const int m = t;
        float gl = b_gate2[0];
        float al = b_attn2[0];
        #pragma unroll
        for (int h = 0; h < 8; h++) {
            float yg = Ys[m * YS_STRIDE + 64 + h];
            float v  = fmaf(g_gate[h], yg, b_gate[h]);
            v = (v >= 0.0f) ? v : 0.2f * v;
            gl = fmaf(w_gate2[h], v, gl);
            float ya = Ys[m * YS_STRIDE + 72 + h];
            float u  = fmaf(g_attn[h], ya, b_attn[h]);
            u = (u >= 0.0f) ? u : 0.2f * u;
            al = fmaf(w_attn2[h], u, al);
        }
        gate_out[b * (N_ * K_) + nb * K_ + m] = gl;

        float amax = al;
        #pragma unroll
        for (int s = 16; s > 0; s >>= 1)
            amax = fmaxf(amax, __shfl_xor_sync(0xffffffffu, amax, s));
        float e = __expf(al - amax);
        float S = e;
        #pragma unroll
        for (int s = 16; s > 0; s >>= 1)
            S += __shfl_xor_sync(0xffffffffu, S, s);
        float w  = e / S;
        float wm = (gl >= 0.0f) ? w : 0.0f;
        float Sm = wm;
        #pragma unroll
        for (int s = 16; s > 0; s >>= 1)
            Sm += __shfl_xor_sync(0xffffffffu, Sm, s);
        WF[m] = wm / (Sm + 1e-6f);
    }
    __syncthreads();

    // ---- phase C: affine + lrelu, weighted sum + max over k (2 n-rows/thread) ----
    const float alpha = 1.0f / (1.0f + __expf(-agg_alpha[0]));
    float* Obuf = (float*)(smem + SM_OBUF);
    {
        const int o = t & 63;
        const float g  = g_trans[o];
        const float bb = b_trans[o];
        #pragma unroll
        for (int half = 0; half < 2; half++) {
            const int nn = (t >> 6) + 4 * half;
            const int mBase = nn * K_;
            float s  = 0.0f;
            float mx = -INFINITY;
            #pragma unroll
            for (int k = 0; k < K_; k++) {
                float y  = Ys[(mBase + k) * YS_STRIDE + o];
                float tv = fmaf(g, y, bb);
                tv = (tv >= 0.0f) ? tv : 0.2f * tv;
                s  = fmaf(tv, WF[mBase + k], s);
                mx = fmaxf(mx, tv);
            }
            Obuf[o * 9 + nn] = alpha * s + (1.0f - alpha) * mx;
        }
    }
    __syncthreads();

    if (t < 128) {
        const int o = t >> 1, h = t & 1;
        float4 v;
        v.x = Obuf[o * 9 + 4 * h];
        v.y = Obuf[o * 9 + 4 * h + 1];
        v.z = Obuf[o * 9 + 4 * h + 2];
        v.w = Obuf[o * 9 + 4 * h + 3];
        *(float4*)(out + (b * O_ + o) * N_ + nb + 4 * h) = v;
    }
}

extern "C" void kernel_launch(void* const* d_in, const int* in_sizes, int n_in,
                              void* d_out, int out_size) {
    const float* x        = (const float*)d_in[0];
    const float* w_trans  = (const float*)d_in[1];
    const float* g_trans  = (const float*)d_in[2];
    const float* b_trans  = (const float*)d_in[3];
    const float* w_gate1  = (const float*)d_in[4];
    const float* g_gate   = (const float*)d_in[5];
    const float* b_gate   = (const float*)d_in[6];
    const float* w_gate2  = (const float*)d_in[7];
    const float* b_gate2  = (const float*)d_in[8];
    const float* w_attn1  = (const float*)d_in[9];
    const float* g_attn   = (const float*)d_in[10];
    const float* b_attn   = (const float*)d_in[11];
    const float* w_attn2  = (const float*)d_in[12];
    const float* b_attn2  = (const float*)d_in[13];
    const float* agg_alpha= (const float*)d_in[14];

    float* out      = (float*)d_out;                  // [B,O,N]
    float* gate_out = out + (size_t)B_ * O_ * N_;     // [B,1,N,K]

    cudaFuncSetAttribute(gsl_mma, cudaFuncAttributeMaxDynamicSharedMemorySize, SM_TOTAL);

    prep_b<<<(NH_ * C_ + 255) / 256, 256>>>(w_trans, w_gate1, w_attn1);
    gsl_mma<<<B_ * (N_ / TN_), 256, SM_TOTAL>>>(
        x, g_trans, b_trans, g_gate, b_gate, w_gate2, b_gate2,
        g_attn, b_attn, w_attn2, b_attn2, agg_alpha, out, gate_out);
}

// round 7
// speedup vs baseline: 1.2376x; 1.0910x over previous
#include <cuda_runtime.h>
#include <cuda_fp16.h>
#include <cstdint>
#include <math.h>

#define B_   8
#define N_   4096
#define K_   32
#define C_   128
#define O_   64
#define NH_  80
#define TN_  8
#define M2_  256            // positions per block
#define NT_  512            // threads per block

// ---- smem layout (bytes) ----
#define SM_W    0           // 24576: W hi (80x128 fp16, 20480) + W lo for o>=64 (16x128, 4096)
#define SM_WLO  20480
#define SM_XB   24576       // 2 bufs x 32768: 32c x 256m fp16 (hi 16384 + lo 16384)
#define SM_WF   90112       // 256 floats
#define SM_OBUF 91136       // 64 x 9 floats = 2304
#define SM_TOTAL 93440
#define SM_YS   0           // overlay (after last MMA): 256 x 81 floats = 82944
#define YS_STRIDE 81

__device__ __forceinline__ uint32_t smem_u32(const void* p) {
    uint32_t a;
    asm("{ .reg .u64 t; cvta.to.shared.u64 t, %1; cvt.u32.u64 %0, t; }" : "=r"(a) : "l"(p));
    return a;
}

#define LDSM_X4(r, a) \
    asm volatile("ldmatrix.sync.aligned.m8n8.x4.shared.b16 {%0,%1,%2,%3}, [%4];" \
        : "=r"((r)[0]), "=r"((r)[1]), "=r"((r)[2]), "=r"((r)[3]) : "r"(a))
#define LDSM_X4_T(r, a) \
    asm volatile("ldmatrix.sync.aligned.m8n8.x4.trans.shared.b16 {%0,%1,%2,%3}, [%4];" \
        : "=r"((r)[0]), "=r"((r)[1]), "=r"((r)[2]), "=r"((r)[3]) : "r"(a))
#define MMA_F16(c, a, b0, b1) \
    asm volatile("mma.sync.aligned.m16n8k16.row.col.f32.f16.f16.f32 " \
        "{%0,%1,%2,%3},{%4,%5,%6,%7},{%8,%9},{%0,%1,%2,%3};" \
        : "+f"((c)[0]), "+f"((c)[1]), "+f"((c)[2]), "+f"((c)[3]) \
        : "r"((a)[0]), "r"((a)[1]), "r"((a)[2]), "r"((a)[3]), "r"(b0), "r"(b1))

// ================= weight prep =================
// W hi: byte(o,c) = o*256 + (((c>>3) ^ (o&7))<<4) + (c&7)*2  (fp16)
// W lo: only head channels o in [64,80): at SM_WLO + (o-64)*256 + same inner swizzle
__device__ uint4 g_Wimg[1536];   // 24576 B

__global__ void prep_b(const float* __restrict__ wt, const float* __restrict__ wg,
                       const float* __restrict__ wa) {
    int i = blockIdx.x * blockDim.x + threadIdx.x;
    if (i >= NH_ * C_) return;
    int o = i >> 7, c = i & 127;
    float w = (o < 64) ? wt[o * C_ + c]
            : (o < 72) ? wg[(o - 64) * C_ + c]
                       : wa[(o - 72) * C_ + c];
    __half h = __float2half_rn(w);
    unsigned inner = ((((unsigned)(c >> 3) ^ (o & 7)) << 4)) + (c & 7) * 2u;
    __half* base = (__half*)g_Wimg;
    base[((unsigned)o * 256u + inner) >> 1] = h;
    if (o >= 64) {
        __half l = __float2half_rn(w - __half2float(h));
        base[(20480u + (unsigned)(o - 64) * 256u + inner) >> 1] = l;
    }
}

// STS one 32c chunk (hi+lo fp16 planes), 4 c-rows per thread
__device__ __forceinline__ void sts_chunk(char* base, const float4* stg, int crow, int q) {
    #pragma unroll
    for (int it = 0; it < 4; it++) {
        int c = crow + it * 8;
        float4 v = stg[it];
        __half h0 = __float2half_rn(v.x), h1 = __float2half_rn(v.y);
        __half h2 = __float2half_rn(v.z), h3 = __float2half_rn(v.w);
        __half l0 = __float2half_rn(v.x - __half2float(h0));
        __half l1 = __float2half_rn(v.y - __half2float(h1));
        __half l2 = __float2half_rn(v.z - __half2float(h2));
        __half l3 = __float2half_rn(v.w - __half2float(h3));
        uint2 ph, pl;
        ph.x = (uint32_t)__half_as_ushort(h0) | ((uint32_t)__half_as_ushort(h1) << 16);
        ph.y = (uint32_t)__half_as_ushort(h2) | ((uint32_t)__half_as_ushort(h3) << 16);
        pl.x = (uint32_t)__half_as_ushort(l0) | ((uint32_t)__half_as_ushort(l1) << 16);
        pl.y = (uint32_t)__half_as_ushort(l2) | ((uint32_t)__half_as_ushort(l3) << 16);
        unsigned off = (unsigned)c * 512u + ((((unsigned)(q >> 1)) ^ (c & 7)) << 4) + (q & 1) * 8u;
        *(uint2*)(base + off) = ph;
        *(uint2*)(base + 16384 + off) = pl;
    }
}

// ================= main kernel =================
__global__ __launch_bounds__(NT_, 1)
void gsl_mma(const float* __restrict__ x,
             const float* __restrict__ g_trans, const float* __restrict__ b_trans,
             const float* __restrict__ g_gate,  const float* __restrict__ b_gate,
             const float* __restrict__ w_gate2, const float* __restrict__ b_gate2,
             const float* __restrict__ g_attn,  const float* __restrict__ b_attn,
             const float* __restrict__ w_attn2, const float* __restrict__ b_attn2,
             const float* __restrict__ agg_alpha,
             float* __restrict__ out, float* __restrict__ gate_out)
{
    extern __shared__ char smem[];
    const uint32_t sb = smem_u32(smem);
    const int t    = threadIdx.x;
    const int wid  = t >> 5;     // 0..15, each warp: 16m x 80n
    const int lane = t & 31;
    const int blk  = blockIdx.x;
    const int b    = blk >> 9;
    const int nb   = (blk & 511) * TN_;

    const int xbase = b * (C_ * N_ * K_) + nb * K_;
    const int crow  = t >> 6;          // 0..7: c row (mod 8)
    const int q     = t & 63;          // float4 index within 256m row

    // ---- prologue: issue ALL LDGs (weights + chunk 0) before any STS ----
    uint4 wstg[3];
    #pragma unroll
    for (int i = 0; i < 3; i++) wstg[i] = g_Wimg[t + NT_ * i];
    float4 stg[4];
    #pragma unroll
    for (int it = 0; it < 4; it++) {
        int c = crow + it * 8;
        stg[it] = *(const float4*)(x + xbase + c * (N_ * K_) + q * 4);
    }
    {
        uint4* d = (uint4*)smem;
        #pragma unroll
        for (int i = 0; i < 3; i++) d[t + NT_ * i] = wstg[i];
    }
    sts_chunk(smem + SM_XB, stg, crow, q);
    __syncthreads();

    // ---- fragment addressing ----
    const int l7   = lane & 7;
    const int koff = (lane >> 3) & 1;
    const int r16  = l7 + ((lane & 16) >> 1);
    const uint32_t aBase  = sb + SM_XB + r16 * 512 + ((((unsigned)(2 * wid + koff)) ^ l7) << 4);
    const uint32_t bRowHi = sb + SM_W + r16 * 256;
    const uint32_t bRowLo = sb + SM_WLO + r16 * 256;

    float acc[10][4];
    #pragma unroll
    for (int i = 0; i < 10; i++)
        #pragma unroll
        for (int j = 0; j < 4; j++) acc[i][j] = 0.0f;

    // ---- pipelined mainloop: 4 steps of 32 c ----
    #pragma unroll
    for (int s = 0; s < 4; s++) {
        if (s < 3) {
            #pragma unroll
            for (int it = 0; it < 4; it++) {
                int c = 32 * (s + 1) + crow + it * 8;
                stg[it] = *(const float4*)(x + xbase + c * (N_ * K_) + q * 4);
            }
        }
        const uint32_t xb = (uint32_t)(s & 1) * 32768u;
        #pragma unroll
        for (int g = 0; g < 2; g++) {
            uint32_t ah[4], al[4];
            LDSM_X4_T(ah, aBase + xb + g * 8192u);
            LDSM_X4_T(al, aBase + xb + g * 8192u + 16384u);
            const int st16 = 2 * s + g;
            const uint32_t cs = ((((unsigned)(2 * st16 + koff)) ^ l7) << 4);
            // trans (jp 0..3): 2-pass  (x_hi + x_lo) * w_hi
            #pragma unroll
            for (int jp = 0; jp < 4; jp++) {
                uint32_t bh[4];
                LDSM_X4(bh, bRowHi + jp * 4096 + cs);
                MMA_F16(acc[2 * jp],     ah, bh[0], bh[1]);
                MMA_F16(acc[2 * jp + 1], ah, bh[2], bh[3]);
                MMA_F16(acc[2 * jp],     al, bh[0], bh[1]);
                MMA_F16(acc[2 * jp + 1], al, bh[2], bh[3]);
            }
            // heads (jp 4): 3-pass   + x_hi * w_lo
            {
                uint32_t bh[4], bl[4];
                LDSM_X4(bh, bRowHi + 4 * 4096 + cs);
                LDSM_X4(bl, bRowLo + cs);
                MMA_F16(acc[8], ah, bh[0], bh[1]);
                MMA_F16(acc[9], ah, bh[2], bh[3]);
                MMA_F16(acc[8], al, bh[0], bh[1]);
                MMA_F16(acc[9], al, bh[2], bh[3]);
                MMA_F16(acc[8], ah, bl[0], bl[1]);
                MMA_F16(acc[9], ah, bl[2], bl[3]);
            }
        }
        if (s < 3)
            sts_chunk(smem + SM_XB + (((s + 1) & 1) ? 32768 : 0), stg, crow, q);
        __syncthreads();
    }

    // ---- scatter accumulators to Ys[m][o] (overlay, safe post-sync) ----
    float* Ys = (float*)(smem + SM_YS);
    {
        const int m0  = 16 * wid + (lane >> 2);
        const int nb4 = 2 * (lane & 3);
        #pragma unroll
        for (int jj = 0; jj < 10; jj++) {
            const int n0 = 8 * jj + nb4;
            Ys[m0 * YS_STRIDE + n0]           = acc[jj][0];
            Ys[m0 * YS_STRIDE + n0 + 1]       = acc[jj][1];
            Ys[(m0 + 8) * YS_STRIDE + n0]     = acc[jj][2];
            Ys[(m0 + 8) * YS_STRIDE + n0 + 1] = acc[jj][3];
        }
    }
    __syncthreads();

    // ---- phase A+B: heads + masked softmax (warp = n-row, lane = k), m = t<256 ----
    float* WF = (float*)(smem + SM_WF);
    if (t < M2_) {
        const int m = t;
        float gl = b_gate2[0];
        float al = b_attn2[0];
        #pragma unroll
        for (int h = 0; h < 8; h++) {
            float yg = Ys[m * YS_STRIDE + 64 + h];
            float v  = fmaf(g_gate[h], yg, b_gate[h]);
            v = (v >= 0.0f) ? v : 0.2f * v;
            gl = fmaf(w_gate2[h], v, gl);
            float ya = Ys[m * YS_STRIDE + 72 + h];
            float u  = fmaf(g_attn[h], ya, b_attn[h]);
            u = (u >= 0.0f) ? u : 0.2f * u;
            al = fmaf(w_attn2[h], u, al);
        }
        gate_out[b * (N_ * K_) + nb * K_ + m] = gl;

        float amax = al;
        #pragma unroll
        for (int s = 16; s > 0; s >>= 1)
            amax = fmaxf(amax, __shfl_xor_sync(0xffffffffu, amax, s));
        float e = __expf(al - amax);
        float S = e;
        #pragma unroll
        for (int s = 16; s > 0; s >>= 1)
            S += __shfl_xor_sync(0xffffffffu, S, s);
        float w  = e / S;
        float wm = (gl >= 0.0f) ? w : 0.0f;
        float Sm = wm;
        #pragma unroll
        for (int s = 16; s > 0; s >>= 1)
            Sm += __shfl_xor_sync(0xffffffffu, Sm, s);
        WF[m] = wm / (Sm + 1e-6f);
    }
    __syncthreads();

    // ---- phase C: affine + lrelu, weighted sum + max over k (512 thr = 64o x 8n) ----
    const float alpha = 1.0f / (1.0f + __expf(-agg_alpha[0]));
    float* Obuf = (float*)(smem + SM_OBUF);
    {
        const int o  = t & 63;
        const int nn = t >> 6;       // 0..7
        const float g  = g_trans[o];
        const float bb = b_trans[o];
        const int mBase = nn * K_;
        float s  = 0.0f;
        float mx = -INFINITY;
        #pragma unroll
        for (int k = 0; k < K_; k++) {
            float y  = Ys[(mBase + k) * YS_STRIDE + o];
            float tv = fmaf(g, y, bb);
            tv = (tv >= 0.0f) ? tv : 0.2f * tv;
            s  = fmaf(tv, WF[mBase + k], s);
            mx = fmaxf(mx, tv);
        }
        Obuf[o * 9 + nn] = alpha * s + (1.0f - alpha) * mx;
    }
    __syncthreads();

    if (t < 128) {
        const int o = t >> 1, h = t & 1;
        float4 v;
        v.x = Obuf[o * 9 + 4 * h];
        v.y = Obuf[o * 9 + 4 * h + 1];
        v.z = Obuf[o * 9 + 4 * h + 2];
        v.w = Obuf[o * 9 + 4 * h + 3];
        *(float4*)(out + (b * O_ + o) * N_ + nb + 4 * h) = v;
    }
}

extern "C" void kernel_launch(void* const* d_in, const int* in_sizes, int n_in,
                              void* d_out, int out_size) {
    const float* x        = (const float*)d_in[0];
    const float* w_trans  = (const float*)d_in[1];
    const float* g_trans  = (const float*)d_in[2];
    const float* b_trans  = (const float*)d_in[3];
    const float* w_gate1  = (const float*)d_in[4];
    const float* g_gate   = (const float*)d_in[5];
    const float* b_gate   = (const float*)d_in[6];
    const float* w_gate2  = (const float*)d_in[7];
    const float* b_gate2  = (const float*)d_in[8];
    const float* w_attn1  = (const float*)d_in[9];
    const float* g_attn   = (const float*)d_in[10];
    const float* b_attn   = (const float*)d_in[11];
    const float* w_attn2  = (const float*)d_in[12];
    const float* b_attn2  = (const float*)d_in[13];
    const float* agg_alpha= (const float*)d_in[14];

    float* out      = (float*)d_out;                  // [B,O,N]
    float* gate_out = out + (size_t)B_ * O_ * N_;     // [B,1,N,K]

    cudaFuncSetAttribute(gsl_mma, cudaFuncAttributeMaxDynamicSharedMemorySize, SM_TOTAL);

    prep_b<<<(NH_ * C_ + 255) / 256, 256>>>(w_trans, w_gate1, w_attn1);
    gsl_mma<<<B_ * (N_ / TN_), NT_, SM_TOTAL>>>(
        x, g_trans, b_trans, g_gate, b_gate, w_gate2, b_gate2,
        g_attn, b_attn, w_attn2, b_attn2, agg_alpha, out, gate_out);
}

// round 8
// speedup vs baseline: 1.2496x; 1.0098x over previous
#include <cuda_runtime.h>
#include <cuda_fp16.h>
#include <cstdint>
#include <math.h>

#define B_   8
#define N_   4096
#define K_   32
#define C_   128
#define O_   64
#define NH_  80
#define TN_  8
#define M2_  256            // positions per block
#define NT_  512            // threads per block

// ---- smem layout (bytes) ----
#define SM_W    0           // W hi (80x128 fp16, 20480) + W lo for o>=64 (16x128, 4096)
#define SM_WLO  20480
#define SM_XB   24576       // 2 bufs x 32768: 32c x 256m fp16 (hi 16384 + lo 16384)
#define SM_WF   90112       // 256 floats
#define SM_OBUF 91136       // 64 x 9 floats
#define SM_TOTAL 93440
#define SM_YS   0           // overlay (after last MMA): 256 x 81 floats = 82944
#define YS_STRIDE 81

__device__ __forceinline__ uint32_t smem_u32(const void* p) {
    uint32_t a;
    asm("{ .reg .u64 t; cvta.to.shared.u64 t, %1; cvt.u32.u64 %0, t; }" : "=r"(a) : "l"(p));
    return a;
}

#define LDSM_X4(r, a) \
    asm volatile("ldmatrix.sync.aligned.m8n8.x4.shared.b16 {%0,%1,%2,%3}, [%4];" \
        : "=r"((r)[0]), "=r"((r)[1]), "=r"((r)[2]), "=r"((r)[3]) : "r"(a))
#define LDSM_X4_T(r, a) \
    asm volatile("ldmatrix.sync.aligned.m8n8.x4.trans.shared.b16 {%0,%1,%2,%3}, [%4];" \
        : "=r"((r)[0]), "=r"((r)[1]), "=r"((r)[2]), "=r"((r)[3]) : "r"(a))
#define MMA_F16(c, a, b0, b1) \
    asm volatile("mma.sync.aligned.m16n8k16.row.col.f32.f16.f16.f32 " \
        "{%0,%1,%2,%3},{%4,%5,%6,%7},{%8,%9},{%0,%1,%2,%3};" \
        : "+f"((c)[0]), "+f"((c)[1]), "+f"((c)[2]), "+f"((c)[3]) \
        : "r"((a)[0]), "r"((a)[1]), "r"((a)[2]), "r"((a)[3]), "r"(b0), "r"(b1))

// ================= weight prep (same image as R7) =================
__device__ uint4 g_Wimg[1536];   // 24576 B

__global__ void prep_b(const float* __restrict__ wt, const float* __restrict__ wg,
                       const float* __restrict__ wa) {
    int i = blockIdx.x * blockDim.x + threadIdx.x;
    if (i >= NH_ * C_) return;
    int o = i >> 7, c = i & 127;
    float w = (o < 64) ? wt[o * C_ + c]
            : (o < 72) ? wg[(o - 64) * C_ + c]
                       : wa[(o - 72) * C_ + c];
    __half h = __float2half_rn(w);
    unsigned inner = ((((unsigned)(c >> 3) ^ (o & 7)) << 4)) + (c & 7) * 2u;
    __half* base = (__half*)g_Wimg;
    base[((unsigned)o * 256u + inner) >> 1] = h;
    if (o >= 64) {
        __half l = __float2half_rn(w - __half2float(h));
        base[(20480u + (unsigned)(o - 64) * 256u + inner) >> 1] = l;
    }
}

// STS one 32c chunk (hi+lo fp16 planes), 4 c-rows per thread
__device__ __forceinline__ void sts_chunk(char* base, const float4* stg, int crow, int q) {
    #pragma unroll
    for (int it = 0; it < 4; it++) {
        int c = crow + it * 8;
        float4 v = stg[it];
        __half h0 = __float2half_rn(v.x), h1 = __float2half_rn(v.y);
        __half h2 = __float2half_rn(v.z), h3 = __float2half_rn(v.w);
        __half l0 = __float2half_rn(v.x - __half2float(h0));
        __half l1 = __float2half_rn(v.y - __half2float(h1));
        __half l2 = __float2half_rn(v.z - __half2float(h2));
        __half l3 = __float2half_rn(v.w - __half2float(h3));
        uint2 ph, pl;
        ph.x = (uint32_t)__half_as_ushort(h0) | ((uint32_t)__half_as_ushort(h1) << 16);
        ph.y = (uint32_t)__half_as_ushort(h2) | ((uint32_t)__half_as_ushort(h3) << 16);
        pl.x = (uint32_t)__half_as_ushort(l0) | ((uint32_t)__half_as_ushort(l1) << 16);
        pl.y = (uint32_t)__half_as_ushort(l2) | ((uint32_t)__half_as_ushort(l3) << 16);
        unsigned off = (unsigned)c * 512u + ((((unsigned)(q >> 1)) ^ (c & 7)) << 4) + (q & 1) * 8u;
        *(uint2*)(base + off) = ph;
        *(uint2*)(base + 16384 + off) = pl;
    }
}

// ================= main kernel =================
__global__ __launch_bounds__(NT_, 1)
void gsl_mma(const float* __restrict__ x,
             const float* __restrict__ g_trans, const float* __restrict__ b_trans,
             const float* __restrict__ g_gate,  const float* __restrict__ b_gate,
             const float* __restrict__ w_gate2, const float* __restrict__ b_gate2,
             const float* __restrict__ g_attn,  const float* __restrict__ b_attn,
             const float* __restrict__ w_attn2, const float* __restrict__ b_attn2,
             const float* __restrict__ agg_alpha,
             float* __restrict__ out, float* __restrict__ gate_out)
{
    extern __shared__ char smem[];
    const uint32_t sb = smem_u32(smem);
    const int t    = threadIdx.x;
    const int wid  = t >> 5;
    const int lane = t & 31;
    const int mw   = wid & 7;       // m-group: rows mw*32 .. mw*32+31
    const int nw   = wid >> 3;      // 0: o 0..47 (trans), 1: o 48..79 (trans+heads)
    const int blk  = blockIdx.x;
    const int b    = blk >> 9;
    const int nb   = (blk & 511) * TN_;

    const int xbase = b * (C_ * N_ * K_) + nb * K_;
    const int crow  = t >> 6;          // 0..7: c row (mod 8)
    const int q     = t & 63;          // float4 index within 256m row

    // ---- prologue: issue ALL LDGs (weights + chunk 0) before any STS ----
    uint4 wstg[3];
    #pragma unroll
    for (int i = 0; i < 3; i++) wstg[i] = g_Wimg[t + NT_ * i];
    float4 stg[4];
    #pragma unroll
    for (int it = 0; it < 4; it++) {
        int c = crow + it * 8;
        stg[it] = *(const float4*)(x + xbase + c * (N_ * K_) + q * 4);
    }
    {
        uint4* d = (uint4*)smem;
        #pragma unroll
        for (int i = 0; i < 3; i++) d[t + NT_ * i] = wstg[i];
    }
    sts_chunk(smem + SM_XB, stg, crow, q);
    __syncthreads();

    // ---- fragment addressing ----
    const int l7   = lane & 7;
    const int koff = (lane >> 3) & 1;
    const int r16  = l7 + ((lane & 16) >> 1);
    uint32_t aBase[2];
    #pragma unroll
    for (int mt = 0; mt < 2; mt++)
        aBase[mt] = sb + SM_XB + r16 * 512 + ((((unsigned)(4 * mw + 2 * mt + koff)) ^ l7) << 4);
    const uint32_t bRowHi = sb + SM_W + r16 * 256;
    const uint32_t bRowLo = sb + SM_WLO + r16 * 256;

    // acc[mt][jj][4]: nw0 uses jj 0..5 (o 0..47), nw1 uses jj 0..3 (o 48..79)
    float acc[2][6][4];
    #pragma unroll
    for (int mt = 0; mt < 2; mt++)
        #pragma unroll
        for (int i = 0; i < 6; i++)
            #pragma unroll
            for (int j = 0; j < 4; j++) acc[mt][i][j] = 0.0f;

    // ---- pipelined mainloop: 4 steps of 32 c ----
    #pragma unroll
    for (int s = 0; s < 4; s++) {
        if (s < 3) {
            #pragma unroll
            for (int it = 0; it < 4; it++) {
                int c = 32 * (s + 1) + crow + it * 8;
                stg[it] = *(const float4*)(x + xbase + c * (N_ * K_) + q * 4);
            }
        }
        const uint32_t xb = (uint32_t)(s & 1) * 32768u;
        #pragma unroll
        for (int g = 0; g < 2; g++) {
            const int st16 = 2 * s + g;
            const uint32_t cs = ((((unsigned)(2 * st16 + koff)) ^ l7) << 4);
            uint32_t ah[2][4];
            #pragma unroll
            for (int mt = 0; mt < 2; mt++)
                LDSM_X4_T(ah[mt], aBase[mt] + xb + g * 8192u);
            if (nw == 0) {
                // trans o 0..47, single-pass x_hi * w_hi
                #pragma unroll
                for (int jp = 0; jp < 3; jp++) {
                    uint32_t bh[4];
                    LDSM_X4(bh, bRowHi + jp * 4096 + cs);
                    #pragma unroll
                    for (int mt = 0; mt < 2; mt++) {
                        MMA_F16(acc[mt][2 * jp],     ah[mt], bh[0], bh[1]);
                        MMA_F16(acc[mt][2 * jp + 1], ah[mt], bh[2], bh[3]);
                    }
                }
            } else {
                uint32_t al[2][4];
                #pragma unroll
                for (int mt = 0; mt < 2; mt++)
                    LDSM_X4_T(al[mt], aBase[mt] + xb + g * 8192u + 16384u);
                // trans o 48..63, single-pass
                {
                    uint32_t bh[4];
                    LDSM_X4(bh, bRowHi + 3 * 4096 + cs);
                    #pragma unroll
                    for (int mt = 0; mt < 2; mt++) {
                        MMA_F16(acc[mt][0], ah[mt], bh[0], bh[1]);
                        MMA_F16(acc[mt][1], ah[mt], bh[2], bh[3]);
                    }
                }
                // heads o 64..79: 3-pass exact
                {
                    uint32_t bh[4], bl[4];
                    LDSM_X4(bh, bRowHi + 4 * 4096 + cs);
                    LDSM_X4(bl, bRowLo + cs);
                    #pragma unroll
                    for (int mt = 0; mt < 2; mt++) {
                        MMA_F16(acc[mt][2], ah[mt], bh[0], bh[1]);
                        MMA_F16(acc[mt][3], ah[mt], bh[2], bh[3]);
                        MMA_F16(acc[mt][2], al[mt], bh[0], bh[1]);
                        MMA_F16(acc[mt][3], al[mt], bh[2], bh[3]);
                        MMA_F16(acc[mt][2], ah[mt], bl[0], bl[1]);
                        MMA_F16(acc[mt][3], ah[mt], bl[2], bl[3]);
                    }
                }
            }
        }
        if (s < 3)
            sts_chunk(smem + SM_XB + (((s + 1) & 1) ? 32768 : 0), stg, crow, q);
        __syncthreads();
    }

    // ---- scatter accumulators to Ys[m][o] (overlay, safe post-sync) ----
    float* Ys = (float*)(smem + SM_YS);
    {
        const int m0  = mw * 32 + (lane >> 2);
        const int ob  = nw * 48;
        const int nb4 = 2 * (lane & 3);
        const int njj = nw ? 4 : 6;
        #pragma unroll
        for (int mt = 0; mt < 2; mt++) {
            const int mr = m0 + 16 * mt;
            for (int jj = 0; jj < njj; jj++) {
                const int n0 = ob + 8 * jj + nb4;
                Ys[mr * YS_STRIDE + n0]           = acc[mt][jj][0];
                Ys[mr * YS_STRIDE + n0 + 1]       = acc[mt][jj][1];
                Ys[(mr + 8) * YS_STRIDE + n0]     = acc[mt][jj][2];
                Ys[(mr + 8) * YS_STRIDE + n0 + 1] = acc[mt][jj][3];
            }
        }
    }
    __syncthreads();

    // ---- phase A+B: heads + masked softmax (warp = n-row, lane = k), m = t<256 ----
    float* WF = (float*)(smem + SM_WF);
    if (t < M2_) {
        const int m = t;
        float gl = b_gate2[0];
        float al = b_attn2[0];
        #pragma unroll
        for (int h = 0; h < 8; h++) {
            float yg = Ys[m * YS_STRIDE + 64 + h];
            float v  = fmaf(g_gate[h], yg, b_gate[h]);
            v = (v >= 0.0f) ? v : 0.2f * v;
            gl = fmaf(w_gate2[h], v, gl);
            float ya = Ys[m * YS_STRIDE + 72 + h];
            float u  = fmaf(g_attn[h], ya, b_attn[h]);
            u = (u >= 0.0f) ? u : 0.2f * u;
            al = fmaf(w_attn2[h], u, al);
        }
        gate_out[b * (N_ * K_) + nb * K_ + m] = gl;

        float amax = al;
        #pragma unroll
        for (int s = 16; s > 0; s >>= 1)
            amax = fmaxf(amax, __shfl_xor_sync(0xffffffffu, amax, s));
        float e = __expf(al - amax);
        float S = e;
        #pragma unroll
        for (int s = 16; s > 0; s >>= 1)
            S += __shfl_xor_sync(0xffffffffu, S, s);
        float w  = e / S;
        float wm = (gl >= 0.0f) ? w : 0.0f;
        float Sm = wm;
        #pragma unroll
        for (int s = 16; s > 0; s >>= 1)
            Sm += __shfl_xor_sync(0xffffffffu, Sm, s);
        WF[m] = wm / (Sm + 1e-6f);
    }
    __syncthreads();

    // ---- phase C: affine + lrelu, weighted sum + max over k (512 thr = 64o x 8n) ----
    const float alpha = 1.0f / (1.0f + __expf(-agg_alpha[0]));
    float* Obuf = (float*)(smem + SM_OBUF);
    {
        const int o  = t & 63;
        const int nn = t >> 6;       // 0..7
        const float g  = g_trans[o];
        const float bb = b_trans[o];
        const int mBase = nn * K_;
        float s  = 0.0f;
        float mx = -INFINITY;
        #pragma unroll
        for (int k = 0; k < K_; k++) {
            float y  = Ys[(mBase + k) * YS_STRIDE + o];
            float tv = fmaf(g, y, bb);
            tv = (tv >= 0.0f) ? tv : 0.2f * tv;
            s  = fmaf(tv, WF[mBase + k], s);
            mx = fmaxf(mx, tv);
        }
        Obuf[o * 9 + nn] = alpha * s + (1.0f - alpha) * mx;
    }
    __syncthreads();

    if (t < 128) {
        const int o = t >> 1, h = t & 1;
        float4 v;
        v.x = Obuf[o * 9 + 4 * h];
        v.y = Obuf[o * 9 + 4 * h + 1];
        v.z = Obuf[o * 9 + 4 * h + 2];
        v.w = Obuf[o * 9 + 4 * h + 3];
        *(float4*)(out + (b * O_ + o) * N_ + nb + 4 * h) = v;
    }
}

extern "C" void kernel_launch(void* const* d_in, const int* in_sizes, int n_in,
                              void* d_out, int out_size) {
    const float* x        = (const float*)d_in[0];
    const float* w_trans  = (const float*)d_in[1];
    const float* g_trans  = (const float*)d_in[2];
    const float* b_trans  = (const float*)d_in[3];
    const float* w_gate1  = (const float*)d_in[4];
    const float* g_gate   = (const float*)d_in[5];
    const float* b_gate   = (const float*)d_in[6];
    const float* w_gate2  = (const float*)d_in[7];
    const float* b_gate2  = (const float*)d_in[8];
    const float* w_attn1  = (const float*)d_in[9];
    const float* g_attn   = (const float*)d_in[10];
    const float* b_attn   = (const float*)d_in[11];
    const float* w_attn2  = (const float*)d_in[12];
    const float* b_attn2  = (const float*)d_in[13];
    const float* agg_alpha= (const float*)d_in[14];

    float* out      = (float*)d_out;                  // [B,O,N]
    float* gate_out = out + (size_t)B_ * O_ * N_;     // [B,1,N,K]

    cudaFuncSetAttribute(gsl_mma, cudaFuncAttributeMaxDynamicSharedMemorySize, SM_TOTAL);

    prep_b<<<(NH_ * C_ + 255) / 256, 256>>>(w_trans, w_gate1, w_attn1);
    gsl_mma<<<B_ * (N_ / TN_), NT_, SM_TOTAL>>>(
        x, g_trans, b_trans, g_gate, b_gate, w_gate2, b_gate2,
        g_attn, b_attn, w_attn2, b_attn2, agg_alpha, out, gate_out);
}

// round 9
// speedup vs baseline: 1.4006x; 1.1208x over previous
#include <cuda_runtime.h>
#include <cuda_fp16.h>
#include <cstdint>
#include <math.h>

#define B_   8
#define N_   4096
#define K_   32
#define C_   128
#define O_   64
#define NH_  80
#define TN_  4
#define M2_  128            // positions per block
#define NT_  256            // threads per block

// ---- smem layout (bytes) ----
#define SM_W    0           // W hi (80x128 fp16, 20480) + W lo for o>=64 (16x128, 4096)
#define SM_WLO  20480
#define SM_XB   24576       // 2 bufs x 16384: 32c x 128m fp16 (hi 8192 + lo 8192)
#define SM_WF   57344       // 128 floats
#define SM_OBUF 57856       // 64 x 5 floats = 1280
#define SM_TOTAL 59392
#define SM_YS   0           // overlay (after last MMA): 128 x 81 floats = 41472
#define YS_STRIDE 81

__device__ __forceinline__ uint32_t smem_u32(const void* p) {
    uint32_t a;
    asm("{ .reg .u64 t; cvta.to.shared.u64 t, %1; cvt.u32.u64 %0, t; }" : "=r"(a) : "l"(p));
    return a;
}

#define LDSM_X4(r, a) \
    asm volatile("ldmatrix.sync.aligned.m8n8.x4.shared.b16 {%0,%1,%2,%3}, [%4];" \
        : "=r"((r)[0]), "=r"((r)[1]), "=r"((r)[2]), "=r"((r)[3]) : "r"(a))
#define LDSM_X4_T(r, a) \
    asm volatile("ldmatrix.sync.aligned.m8n8.x4.trans.shared.b16 {%0,%1,%2,%3}, [%4];" \
        : "=r"((r)[0]), "=r"((r)[1]), "=r"((r)[2]), "=r"((r)[3]) : "r"(a))
#define MMA_F16(c, a, b0, b1) \
    asm volatile("mma.sync.aligned.m16n8k16.row.col.f32.f16.f16.f32 " \
        "{%0,%1,%2,%3},{%4,%5,%6,%7},{%8,%9},{%0,%1,%2,%3};" \
        : "+f"((c)[0]), "+f"((c)[1]), "+f"((c)[2]), "+f"((c)[3]) \
        : "r"((a)[0]), "r"((a)[1]), "r"((a)[2]), "r"((a)[3]), "r"(b0), "r"(b1))

// ================= weight prep (same image as R7/R8) =================
__device__ uint4 g_Wimg[1536];   // 24576 B

__global__ void prep_b(const float* __restrict__ wt, const float* __restrict__ wg,
                       const float* __restrict__ wa) {
    int i = blockIdx.x * blockDim.x + threadIdx.x;
    if (i >= NH_ * C_) return;
    int o = i >> 7, c = i & 127;
    float w = (o < 64) ? wt[o * C_ + c]
            : (o < 72) ? wg[(o - 64) * C_ + c]
                       : wa[(o - 72) * C_ + c];
    __half h = __float2half_rn(w);
    unsigned inner = ((((unsigned)(c >> 3) ^ (o & 7)) << 4)) + (c & 7) * 2u;
    __half* base = (__half*)g_Wimg;
    base[((unsigned)o * 256u + inner) >> 1] = h;
    if (o >= 64) {
        __half l = __float2half_rn(w - __half2float(h));
        base[(20480u + (unsigned)(o - 64) * 256u + inner) >> 1] = l;
    }
}

// STS one 32c x 128m chunk (hi+lo fp16 planes), 4 c-rows per thread
__device__ __forceinline__ void sts_chunk(char* base, const float4* stg, int crow, int q) {
    #pragma unroll
    for (int it = 0; it < 4; it++) {
        int c = crow + it * 8;
        float4 v = stg[it];
        __half h0 = __float2half_rn(v.x), h1 = __float2half_rn(v.y);
        __half h2 = __float2half_rn(v.z), h3 = __float2half_rn(v.w);
        __half l0 = __float2half_rn(v.x - __half2float(h0));
        __half l1 = __float2half_rn(v.y - __half2float(h1));
        __half l2 = __float2half_rn(v.z - __half2float(h2));
        __half l3 = __float2half_rn(v.w - __half2float(h3));
        uint2 ph, pl;
        ph.x = (uint32_t)__half_as_ushort(h0) | ((uint32_t)__half_as_ushort(h1) << 16);
        ph.y = (uint32_t)__half_as_ushort(h2) | ((uint32_t)__half_as_ushort(h3) << 16);
        pl.x = (uint32_t)__half_as_ushort(l0) | ((uint32_t)__half_as_ushort(l1) << 16);
        pl.y = (uint32_t)__half_as_ushort(l2) | ((uint32_t)__half_as_ushort(l3) << 16);
        unsigned off = (unsigned)c * 256u + ((((unsigned)(q >> 1)) ^ (c & 7)) << 4) + (q & 1) * 8u;
        *(uint2*)(base + off) = ph;
        *(uint2*)(base + 8192 + off) = pl;
    }
}

// ================= main kernel =================
__global__ __launch_bounds__(NT_, 2)
void gsl_mma(const float* __restrict__ x,
             const float* __restrict__ g_trans, const float* __restrict__ b_trans,
             const float* __restrict__ g_gate,  const float* __restrict__ b_gate,
             const float* __restrict__ w_gate2, const float* __restrict__ b_gate2,
             const float* __restrict__ g_attn,  const float* __restrict__ b_attn,
             const float* __restrict__ w_attn2, const float* __restrict__ b_attn2,
             const float* __restrict__ agg_alpha,
             float* __restrict__ out, float* __restrict__ gate_out)
{
    extern __shared__ char smem[];
    const uint32_t sb = smem_u32(smem);
    const int t    = threadIdx.x;
    const int wid  = t >> 5;
    const int lane = t & 31;
    const int mw   = wid & 3;       // m-group: rows mw*32 .. mw*32+31
    const int nw   = wid >> 2;      // 0: o 0..47 (trans), 1: o 48..79 (trans+heads)
    const int blk  = blockIdx.x;
    const int b    = blk >> 10;
    const int nb   = (blk & 1023) * TN_;

    const int xbase = b * (C_ * N_ * K_) + nb * K_;
    const int crow  = t >> 5;          // 0..7: c row (mod 8)
    const int q     = t & 31;          // float4 index within 128m row

    // ---- prologue: issue ALL LDGs (weights + chunk 0) before any STS ----
    uint4 wstg[6];
    #pragma unroll
    for (int i = 0; i < 6; i++) wstg[i] = g_Wimg[t + NT_ * i];
    float4 stg[4];
    #pragma unroll
    for (int it = 0; it < 4; it++) {
        int c = crow + it * 8;
        stg[it] = *(const float4*)(x + xbase + c * (N_ * K_) + q * 4);
    }
    {
        uint4* d = (uint4*)smem;
        #pragma unroll
        for (int i = 0; i < 6; i++) d[t + NT_ * i] = wstg[i];
    }
    sts_chunk(smem + SM_XB, stg, crow, q);
    __syncthreads();

    // ---- fragment addressing ----
    const int l7   = lane & 7;
    const int koff = (lane >> 3) & 1;
    const int r16  = l7 + ((lane & 16) >> 1);
    uint32_t aBase[2];
    #pragma unroll
    for (int mt = 0; mt < 2; mt++)
        aBase[mt] = sb + SM_XB + r16 * 256 + ((((unsigned)(4 * mw + 2 * mt + koff)) ^ l7) << 4);
    const uint32_t bRowHi = sb + SM_W + r16 * 256;
    const uint32_t bRowLo = sb + SM_WLO + r16 * 256;

    // acc[mt][jj][4]: nw0 uses jj 0..5 (o 0..47), nw1 uses jj 0..3 (o 48..79)
    float acc[2][6][4];
    #pragma unroll
    for (int mt = 0; mt < 2; mt++)
        #pragma unroll
        for (int i = 0; i < 6; i++)
            #pragma unroll
            for (int j = 0; j < 4; j++) acc[mt][i][j] = 0.0f;

    // ---- pipelined mainloop: 4 steps of 32 c ----
    #pragma unroll
    for (int s = 0; s < 4; s++) {
        if (s < 3) {
            #pragma unroll
            for (int it = 0; it < 4; it++) {
                int c = 32 * (s + 1) + crow + it * 8;
                stg[it] = *(const float4*)(x + xbase + c * (N_ * K_) + q * 4);
            }
        }
        const uint32_t xb = (uint32_t)(s & 1) * 16384u;
        #pragma unroll
        for (int g = 0; g < 2; g++) {
            const int st16 = 2 * s + g;
            const uint32_t cs = ((((unsigned)(2 * st16 + koff)) ^ l7) << 4);
            uint32_t ah[2][4];
            #pragma unroll
            for (int mt = 0; mt < 2; mt++)
                LDSM_X4_T(ah[mt], aBase[mt] + xb + g * 4096u);
            if (nw == 0) {
                // trans o 0..47, single-pass x_hi * w_hi
                #pragma unroll
                for (int jp = 0; jp < 3; jp++) {
                    uint32_t bh[4];
                    LDSM_X4(bh, bRowHi + jp * 4096 + cs);
                    #pragma unroll
                    for (int mt = 0; mt < 2; mt++) {
                        MMA_F16(acc[mt][2 * jp],     ah[mt], bh[0], bh[1]);
                        MMA_F16(acc[mt][2 * jp + 1], ah[mt], bh[2], bh[3]);
                    }
                }
            } else {
                uint32_t al[2][4];
                #pragma unroll
                for (int mt = 0; mt < 2; mt++)
                    LDSM_X4_T(al[mt], aBase[mt] + xb + g * 4096u + 8192u);
                // trans o 48..63, single-pass
                {
                    uint32_t bh[4];
                    LDSM_X4(bh, bRowHi + 3 * 4096 + cs);
                    #pragma unroll
                    for (int mt = 0; mt < 2; mt++) {
                        MMA_F16(acc[mt][0], ah[mt], bh[0], bh[1]);
                        MMA_F16(acc[mt][1], ah[mt], bh[2], bh[3]);
                    }
                }
                // heads o 64..79: 3-pass exact
                {
                    uint32_t bh[4], bl[4];
                    LDSM_X4(bh, bRowHi + 4 * 4096 + cs);
                    LDSM_X4(bl, bRowLo + cs);
                    #pragma unroll
                    for (int mt = 0; mt < 2; mt++) {
                        MMA_F16(acc[mt][2], ah[mt], bh[0], bh[1]);
                        MMA_F16(acc[mt][3], ah[mt], bh[2], bh[3]);
                        MMA_F16(acc[mt][2], al[mt], bh[0], bh[1]);
                        MMA_F16(acc[mt][3], al[mt], bh[2], bh[3]);
                        MMA_F16(acc[mt][2], ah[mt], bl[0], bl[1]);
                        MMA_F16(acc[mt][3], ah[mt], bl[2], bl[3]);
                    }
                }
            }
        }
        if (s < 3)
            sts_chunk(smem + SM_XB + (((s + 1) & 1) ? 16384 : 0), stg, crow, q);
        __syncthreads();
    }

    // ---- scatter accumulators to Ys[m][o] (overlay, safe post-sync) ----
    float* Ys = (float*)(smem + SM_YS);
    {
        const int m0  = mw * 32 + (lane >> 2);
        const int ob  = nw * 48;
        const int nb4 = 2 * (lane & 3);
        const int njj = nw ? 4 : 6;
        #pragma unroll
        for (int mt = 0; mt < 2; mt++) {
            const int mr = m0 + 16 * mt;
            for (int jj = 0; jj < njj; jj++) {
                const int n0 = ob + 8 * jj + nb4;
                Ys[mr * YS_STRIDE + n0]           = acc[mt][jj][0];
                Ys[mr * YS_STRIDE + n0 + 1]       = acc[mt][jj][1];
                Ys[(mr + 8) * YS_STRIDE + n0]     = acc[mt][jj][2];
                Ys[(mr + 8) * YS_STRIDE + n0 + 1] = acc[mt][jj][3];
            }
        }
    }
    __syncthreads();

    // ---- phase A+B: heads + masked softmax (warp = n-row, lane = k), m = t<128 ----
    float* WF = (float*)(smem + SM_WF);
    if (t < M2_) {
        const int m = t;
        float gl = b_gate2[0];
        float al = b_attn2[0];
        #pragma unroll
        for (int h = 0; h < 8; h++) {
            float yg = Ys[m * YS_STRIDE + 64 + h];
            float v  = fmaf(g_gate[h], yg, b_gate[h]);
            v = (v >= 0.0f) ? v : 0.2f * v;
            gl = fmaf(w_gate2[h], v, gl);
            float ya = Ys[m * YS_STRIDE + 72 + h];
            float u  = fmaf(g_attn[h], ya, b_attn[h]);
            u = (u >= 0.0f) ? u : 0.2f * u;
            al = fmaf(w_attn2[h], u, al);
        }
        gate_out[b * (N_ * K_) + nb * K_ + m] = gl;

        float amax = al;
        #pragma unroll
        for (int s = 16; s > 0; s >>= 1)
            amax = fmaxf(amax, __shfl_xor_sync(0xffffffffu, amax, s));
        float e = __expf(al - amax);
        float S = e;
        #pragma unroll
        for (int s = 16; s > 0; s >>= 1)
            S += __shfl_xor_sync(0xffffffffu, S, s);
        float w  = e / S;
        float wm = (gl >= 0.0f) ? w : 0.0f;
        float Sm = wm;
        #pragma unroll
        for (int s = 16; s > 0; s >>= 1)
            Sm += __shfl_xor_sync(0xffffffffu, Sm, s);
        WF[m] = wm / (Sm + 1e-6f);
    }
    __syncthreads();

    // ---- phase C: affine + lrelu, weighted sum + max over k (256 thr = 64o x 4n) ----
    const float alpha = 1.0f / (1.0f + __expf(-agg_alpha[0]));
    float* Obuf = (float*)(smem + SM_OBUF);
    {
        const int o  = t & 63;
        const int nn = t >> 6;       // 0..3
        const float g  = g_trans[o];
        const float bb = b_trans[o];
        const int mBase = nn * K_;
        float s  = 0.0f;
        float mx = -INFINITY;
        #pragma unroll
        for (int k = 0; k < K_; k++) {
            float y  = Ys[(mBase + k) * YS_STRIDE + o];
            float tv = fmaf(g, y, bb);
            tv = (tv >= 0.0f) ? tv : 0.2f * tv;
            s  = fmaf(tv, WF[mBase + k], s);
            mx = fmaxf(mx, tv);
        }
        Obuf[o * 5 + nn] = alpha * s + (1.0f - alpha) * mx;
    }
    __syncthreads();

    if (t < 64) {
        float4 v;
        v.x = Obuf[t * 5 + 0];
        v.y = Obuf[t * 5 + 1];
        v.z = Obuf[t * 5 + 2];
        v.w = Obuf[t * 5 + 3];
        *(float4*)(out + (b * O_ + t) * N_ + nb) = v;
    }
}

extern "C" void kernel_launch(void* const* d_in, const int* in_sizes, int n_in,
                              void* d_out, int out_size) {
    const float* x        = (const float*)d_in[0];
    const float* w_trans  = (const float*)d_in[1];
    const float* g_trans  = (const float*)d_in[2];
    const float* b_trans  = (const float*)d_in[3];
    const float* w_gate1  = (const float*)d_in[4];
    const float* g_gate   = (const float*)d_in[5];
    const float* b_gate   = (const float*)d_in[6];
    const float* w_gate2  = (const float*)d_in[7];
    const float* b_gate2  = (const float*)d_in[8];
    const float* w_attn1  = (const float*)d_in[9];
    const float* g_attn   = (const float*)d_in[10];
    const float* b_attn   = (const float*)d_in[11];
    const float* w_attn2  = (const float*)d_in[12];
    const float* b_attn2  = (const float*)d_in[13];
    const float* agg_alpha= (const float*)d_in[14];

    float* out      = (float*)d_out;                  // [B,O,N]
    float* gate_out = out + (size_t)B_ * O_ * N_;     // [B,1,N,K]

    cudaFuncSetAttribute(gsl_mma, cudaFuncAttributeMaxDynamicSharedMemorySize, SM_TOTAL);

    prep_b<<<(NH_ * C_ + 255) / 256, 256>>>(w_trans, w_gate1, w_attn1);
    gsl_mma<<<B_ * (N_ / TN_), NT_, SM_TOTAL>>>(
        x, g_trans, b_trans, g_gate, b_gate, w_gate2, b_gate2,
        g_attn, b_attn, w_attn2, b_attn2, agg_alpha, out, gate_out);
}

// round 10
// speedup vs baseline: 1.6440x; 1.1738x over previous
#include <cuda_runtime.h>
#include <cuda_fp16.h>
#include <cstdint>
#include <math.h>

#define B_   8
#define N_   4096
#define K_   32
#define C_   128
#define O_   64
#define NH_  80
#define TN_  4
#define M2_  128            // positions per block
#define NT_  256            // threads per block

// ---- smem layout (bytes) ----
#define SM_W    0           // W hi (80x128 fp16, 20480) + W lo for o>=64 (16x128, 4096)
#define SM_WLO  20480
#define SM_XB   24576       // 2 bufs x 16384: 32c x 128m fp16 (hi 8192 + lo 8192)
#define SM_WFS  57344       // 128 floats
#define SM_OBUF 57856       // 64 x 5 floats = 1280
#define SM_TOTAL 59392

__device__ __forceinline__ uint32_t smem_u32(const void* p) {
    uint32_t a;
    asm("{ .reg .u64 t; cvta.to.shared.u64 t, %1; cvt.u32.u64 %0, t; }" : "=r"(a) : "l"(p));
    return a;
}

#define LDSM_X4(r, a) \
    asm volatile("ldmatrix.sync.aligned.m8n8.x4.shared.b16 {%0,%1,%2,%3}, [%4];" \
        : "=r"((r)[0]), "=r"((r)[1]), "=r"((r)[2]), "=r"((r)[3]) : "r"(a))
#define LDSM_X4_T(r, a) \
    asm volatile("ldmatrix.sync.aligned.m8n8.x4.trans.shared.b16 {%0,%1,%2,%3}, [%4];" \
        : "=r"((r)[0]), "=r"((r)[1]), "=r"((r)[2]), "=r"((r)[3]) : "r"(a))
#define MMA_F16(c, a, b0, b1) \
    asm volatile("mma.sync.aligned.m16n8k16.row.col.f32.f16.f16.f32 " \
        "{%0,%1,%2,%3},{%4,%5,%6,%7},{%8,%9},{%0,%1,%2,%3};" \
        : "+f"((c)[0]), "+f"((c)[1]), "+f"((c)[2]), "+f"((c)[3]) \
        : "r"((a)[0]), "r"((a)[1]), "r"((a)[2]), "r"((a)[3]), "r"(b0), "r"(b1))

// ================= weight prep (same image as R7-R9) =================
__device__ uint4 g_Wimg[1536];   // 24576 B

__global__ void prep_b(const float* __restrict__ wt, const float* __restrict__ wg,
                       const float* __restrict__ wa) {
    int i = blockIdx.x * blockDim.x + threadIdx.x;
    if (i >= NH_ * C_) return;
    int o = i >> 7, c = i & 127;
    float w = (o < 64) ? wt[o * C_ + c]
            : (o < 72) ? wg[(o - 64) * C_ + c]
                       : wa[(o - 72) * C_ + c];
    __half h = __float2half_rn(w);
    unsigned inner = ((((unsigned)(c >> 3) ^ (o & 7)) << 4)) + (c & 7) * 2u;
    __half* base = (__half*)g_Wimg;
    base[((unsigned)o * 256u + inner) >> 1] = h;
    if (o >= 64) {
        __half l = __float2half_rn(w - __half2float(h));
        base[(20480u + (unsigned)(o - 64) * 256u + inner) >> 1] = l;
    }
}

// STS one 32c x 128m chunk (hi+lo fp16 planes), 4 c-rows per thread
__device__ __forceinline__ void sts_chunk(char* base, const float4* stg, int crow, int q) {
    #pragma unroll
    for (int it = 0; it < 4; it++) {
        int c = crow + it * 8;
        float4 v = stg[it];
        __half h0 = __float2half_rn(v.x), h1 = __float2half_rn(v.y);
        __half h2 = __float2half_rn(v.z), h3 = __float2half_rn(v.w);
        __half l0 = __float2half_rn(v.x - __half2float(h0));
        __half l1 = __float2half_rn(v.y - __half2float(h1));
        __half l2 = __float2half_rn(v.z - __half2float(h2));
        __half l3 = __float2half_rn(v.w - __half2float(h3));
        uint2 ph, pl;
        ph.x = (uint32_t)__half_as_ushort(h0) | ((uint32_t)__half_as_ushort(h1) << 16);
        ph.y = (uint32_t)__half_as_ushort(h2) | ((uint32_t)__half_as_ushort(h3) << 16);
        pl.x = (uint32_t)__half_as_ushort(l0) | ((uint32_t)__half_as_ushort(l1) << 16);
        pl.y = (uint32_t)__half_as_ushort(l2) | ((uint32_t)__half_as_ushort(l3) << 16);
        unsigned off = (unsigned)c * 256u + ((((unsigned)(q >> 1)) ^ (c & 7)) << 4) + (q & 1) * 8u;
        *(uint2*)(base + off) = ph;
        *(uint2*)(base + 8192 + off) = pl;
    }
}

// ================= main kernel =================
__global__ __launch_bounds__(NT_, 2)
void gsl_mma(const float* __restrict__ x,
             const float* __restrict__ g_trans, const float* __restrict__ b_trans,
             const float* __restrict__ g_gate,  const float* __restrict__ b_gate,
             const float* __restrict__ w_gate2, const float* __restrict__ b_gate2,
             const float* __restrict__ g_attn,  const float* __restrict__ b_attn,
             const float* __restrict__ w_attn2, const float* __restrict__ b_attn2,
             const float* __restrict__ agg_alpha,
             float* __restrict__ out, float* __restrict__ gate_out)
{
    extern __shared__ char smem[];
    const uint32_t sb = smem_u32(smem);
    const int t    = threadIdx.x;
    const int wid  = t >> 5;
    const int lane = t & 31;
    const int mw   = wid & 3;       // n-row within block; rows mw*32..mw*32+31 (k=0..31)
    const int nw   = wid >> 2;      // 0: o 0..47 (trans), 1: o 48..79 (trans+heads)
    const int blk  = blockIdx.x;
    const int b    = blk >> 10;
    const int nb   = (blk & 1023) * TN_;

    const int xbase = b * (C_ * N_ * K_) + nb * K_;
    const int crow  = t >> 5;          // 0..7: c row (mod 8)
    const int q32   = t & 31;          // float4 index within 128m row

    // ---- prologue: issue ALL LDGs (weights + chunk 0) before any STS ----
    uint4 wstg[6];
    #pragma unroll
    for (int i = 0; i < 6; i++) wstg[i] = g_Wimg[t + NT_ * i];
    float4 stg[4];
    #pragma unroll
    for (int it = 0; it < 4; it++) {
        int c = crow + it * 8;
        stg[it] = *(const float4*)(x + xbase + c * (N_ * K_) + q32 * 4);
    }
    {
        uint4* d = (uint4*)smem;
        #pragma unroll
        for (int i = 0; i < 6; i++) d[t + NT_ * i] = wstg[i];
    }
    sts_chunk(smem + SM_XB, stg, crow, q32);
    __syncthreads();

    // ---- fragment addressing ----
    const int l7   = lane & 7;
    const int koff = (lane >> 3) & 1;
    const int r16  = l7 + ((lane & 16) >> 1);
    uint32_t aBase[2];
    #pragma unroll
    for (int mt = 0; mt < 2; mt++)
        aBase[mt] = sb + SM_XB + r16 * 256 + ((((unsigned)(4 * mw + 2 * mt + koff)) ^ l7) << 4);
    const uint32_t bRowHi = sb + SM_W + r16 * 256;
    const uint32_t bRowLo = sb + SM_WLO + r16 * 256;

    float acc[2][6][4];
    #pragma unroll
    for (int mt = 0; mt < 2; mt++)
        #pragma unroll
        for (int i = 0; i < 6; i++)
            #pragma unroll
            for (int j = 0; j < 4; j++) acc[mt][i][j] = 0.0f;

    // ---- pipelined mainloop: 4 steps of 32 c ----
    #pragma unroll
    for (int s = 0; s < 4; s++) {
        if (s < 3) {
            #pragma unroll
            for (int it = 0; it < 4; it++) {
                int c = 32 * (s + 1) + crow + it * 8;
                stg[it] = *(const float4*)(x + xbase + c * (N_ * K_) + q32 * 4);
            }
        }
        const uint32_t xb = (uint32_t)(s & 1) * 16384u;
        #pragma unroll
        for (int g = 0; g < 2; g++) {
            const int st16 = 2 * s + g;
            const uint32_t cs = ((((unsigned)(2 * st16 + koff)) ^ l7) << 4);
            uint32_t ah[2][4];
            #pragma unroll
            for (int mt = 0; mt < 2; mt++)
                LDSM_X4_T(ah[mt], aBase[mt] + xb + g * 4096u);
            if (nw == 0) {
                #pragma unroll
                for (int jp = 0; jp < 3; jp++) {
                    uint32_t bh[4];
                    LDSM_X4(bh, bRowHi + jp * 4096 + cs);
                    #pragma unroll
                    for (int mt = 0; mt < 2; mt++) {
                        MMA_F16(acc[mt][2 * jp],     ah[mt], bh[0], bh[1]);
                        MMA_F16(acc[mt][2 * jp + 1], ah[mt], bh[2], bh[3]);
                    }
                }
            } else {
                uint32_t al[2][4];
                #pragma unroll
                for (int mt = 0; mt < 2; mt++)
                    LDSM_X4_T(al[mt], aBase[mt] + xb + g * 4096u + 8192u);
                {
                    uint32_t bh[4];
                    LDSM_X4(bh, bRowHi + 3 * 4096 + cs);
                    #pragma unroll
                    for (int mt = 0; mt < 2; mt++) {
                        MMA_F16(acc[mt][0], ah[mt], bh[0], bh[1]);
                        MMA_F16(acc[mt][1], ah[mt], bh[2], bh[3]);
                    }
                }
                {
                    uint32_t bh[4], bl[4];
                    LDSM_X4(bh, bRowHi + 4 * 4096 + cs);
                    LDSM_X4(bl, bRowLo + cs);
                    #pragma unroll
                    for (int mt = 0; mt < 2; mt++) {
                        MMA_F16(acc[mt][2], ah[mt], bh[0], bh[1]);
                        MMA_F16(acc[mt][3], ah[mt], bh[2], bh[3]);
                        MMA_F16(acc[mt][2], al[mt], bh[0], bh[1]);
                        MMA_F16(acc[mt][3], al[mt], bh[2], bh[3]);
                        MMA_F16(acc[mt][2], ah[mt], bl[0], bl[1]);
                        MMA_F16(acc[mt][3], ah[mt], bl[2], bl[3]);
                    }
                }
            }
        }
        if (s < 3) {
            sts_chunk(smem + SM_XB + (((s + 1) & 1) ? 16384 : 0), stg, crow, q32);
            __syncthreads();
        }
    }

    // ================= in-register epilogue =================
    // fragment geometry: element acc[mt][jj][2*rh+par] is
    //   k = (lane>>2) + 8*rh + 16*mt   (within n-row mw)
    //   o = ob + 8*jj + 2*(lane&3) + par
    const int qg = lane >> 2;       // 0..7
    const int c4 = lane & 3;        // 0..3
    const float alpha = 1.0f / (1.0f + __expf(-agg_alpha[0]));
    float* WFs  = (float*)(smem + SM_WFS);
    float* Obuf = (float*)(smem + SM_OBUF);

    float WFreg[2][2];

    if (nw == 1) {
        // ---- heads: gate/attn logits per m, softmax+mask+renorm over k ----
        float gl[2][2], al[2][2];
        const float bg2 = b_gate2[0], ba2 = b_attn2[0];
        #pragma unroll
        for (int mt = 0; mt < 2; mt++)
            #pragma unroll
            for (int rh = 0; rh < 2; rh++) {
                float glp = 0.0f, alp = 0.0f;
                #pragma unroll
                for (int j = 0; j < 2; j++) {
                    int oc = 2 * c4 + j;                 // 0..7
                    float yg = acc[mt][2][2 * rh + j];
                    float v = fmaf(g_gate[oc], yg, b_gate[oc]);
                    v = (v >= 0.0f) ? v : 0.2f * v;
                    glp = fmaf(w_gate2[oc], v, glp);
                    float ya = acc[mt][3][2 * rh + j];
                    float u = fmaf(g_attn[oc], ya, b_attn[oc]);
                    u = (u >= 0.0f) ? u : 0.2f * u;
                    alp = fmaf(w_attn2[oc], u, alp);
                }
                glp += __shfl_xor_sync(0xffffffffu, glp, 1);
                glp += __shfl_xor_sync(0xffffffffu, glp, 2);
                alp += __shfl_xor_sync(0xffffffffu, alp, 1);
                alp += __shfl_xor_sync(0xffffffffu, alp, 2);
                gl[mt][rh] = glp + bg2;
                al[mt][rh] = alp + ba2;
            }
        // row max over 32 k
        float amax = fmaxf(fmaxf(al[0][0], al[0][1]), fmaxf(al[1][0], al[1][1]));
        #pragma unroll
        for (int s = 4; s <= 16; s <<= 1)
            amax = fmaxf(amax, __shfl_xor_sync(0xffffffffu, amax, s));
        float e[2][2];
        float S = 0.0f;
        #pragma unroll
        for (int mt = 0; mt < 2; mt++)
            #pragma unroll
            for (int rh = 0; rh < 2; rh++) {
                e[mt][rh] = __expf(al[mt][rh] - amax);
                S += e[mt][rh];
            }
        #pragma unroll
        for (int s = 4; s <= 16; s <<= 1)
            S += __shfl_xor_sync(0xffffffffu, S, s);
        const float invS = 1.0f / S;
        float wm[2][2];
        float Sm = 0.0f;
        #pragma unroll
        for (int mt = 0; mt < 2; mt++)
            #pragma unroll
            for (int rh = 0; rh < 2; rh++) {
                float w = e[mt][rh] * invS;
                wm[mt][rh] = (gl[mt][rh] >= 0.0f) ? w : 0.0f;
                Sm += wm[mt][rh];
            }
        #pragma unroll
        for (int s = 4; s <= 16; s <<= 1)
            Sm += __shfl_xor_sync(0xffffffffu, Sm, s);
        const float rn = 1.0f / (Sm + 1e-6f);
        #pragma unroll
        for (int mt = 0; mt < 2; mt++)
            #pragma unroll
            for (int rh = 0; rh < 2; rh++)
                WFreg[mt][rh] = wm[mt][rh] * rn;
        // publish WF + gate_out (one lane per qg)
        if (c4 == 0) {
            const int gbase = b * (N_ * K_) + (nb + mw) * K_;
            #pragma unroll
            for (int mt = 0; mt < 2; mt++)
                #pragma unroll
                for (int rh = 0; rh < 2; rh++) {
                    int k = qg + 8 * rh + 16 * mt;
                    WFs[mw * 32 + k] = WFreg[mt][rh];
                    gate_out[gbase + k] = gl[mt][rh];
                }
        }
    }
    __syncthreads();

    if (nw == 0) {
        #pragma unroll
        for (int mt = 0; mt < 2; mt++)
            #pragma unroll
            for (int rh = 0; rh < 2; rh++)
                WFreg[mt][rh] = WFs[mw * 32 + qg + 8 * rh + 16 * mt];
    }

    // ---- phase C: trans affine+lrelu, weighted sum + max over k (in-register) ----
    {
        const int ob  = nw * 48;
        const int njj = nw ? 2 : 6;
        for (int jj = 0; jj < njj; jj++) {
            #pragma unroll
            for (int par = 0; par < 2; par++) {
                const int o = ob + 8 * jj + 2 * c4 + par;
                const float g  = g_trans[o];
                const float bb = b_trans[o];
                float s = 0.0f, mx = -INFINITY;
                #pragma unroll
                for (int mt = 0; mt < 2; mt++)
                    #pragma unroll
                    for (int rh = 0; rh < 2; rh++) {
                        float y  = acc[mt][jj][2 * rh + par];
                        float tv = fmaf(g, y, bb);
                        tv = (tv >= 0.0f) ? tv : 0.2f * tv;
                        s  = fmaf(tv, WFreg[mt][rh], s);
                        mx = fmaxf(mx, tv);
                    }
                #pragma unroll
                for (int st = 4; st <= 16; st <<= 1) {
                    s += __shfl_xor_sync(0xffffffffu, s, st);
                    mx = fmaxf(mx, __shfl_xor_sync(0xffffffffu, mx, st));
                }
                if (qg == 0)
                    Obuf[o * 5 + mw] = alpha * s + (1.0f - alpha) * mx;
            }
        }
    }
    __syncthreads();

    if (t < 64) {
        float4 v;
        v.x = Obuf[t * 5 + 0];
        v.y = Obuf[t * 5 + 1];
        v.z = Obuf[t * 5 + 2];
        v.w = Obuf[t * 5 + 3];
        *(float4*)(out + (b * O_ + t) * N_ + nb) = v;
    }
}

extern "C" void kernel_launch(void* const* d_in, const int* in_sizes, int n_in,
                              void* d_out, int out_size) {
    const float* x        = (const float*)d_in[0];
    const float* w_trans  = (const float*)d_in[1];
    const float* g_trans  = (const float*)d_in[2];
    const float* b_trans  = (const float*)d_in[3];
    const float* w_gate1  = (const float*)d_in[4];
    const float* g_gate   = (const float*)d_in[5];
    const float* b_gate   = (const float*)d_in[6];
    const float* w_gate2  = (const float*)d_in[7];
    const float* b_gate2  = (const float*)d_in[8];
    const float* w_attn1  = (const float*)d_in[9];
    const float* g_attn   = (const float*)d_in[10];
    const float* b_attn   = (const float*)d_in[11];
    const float* w_attn2  = (const float*)d_in[12];
    const float* b_attn2  = (const float*)d_in[13];
    const float* agg_alpha= (const float*)d_in[14];

    float* out      = (float*)d_out;                  // [B,O,N]
    float* gate_out = out + (size_t)B_ * O_ * N_;     // [B,1,N,K]

    cudaFuncSetAttribute(gsl_mma, cudaFuncAttributeMaxDynamicSharedMemorySize, SM_TOTAL);

    prep_b<<<(NH_ * C_ + 255) / 256, 256>>>(w_trans, w_gate1, w_attn1);
    gsl_mma<<<B_ * (N_ / TN_), NT_, SM_TOTAL>>>(
        x, g_trans, b_trans, g_gate, b_gate, w_gate2, b_gate2,
        g_attn, b_attn, w_attn2, b_attn2, agg_alpha, out, gate_out);
}

// round 11
// speedup vs baseline: 1.8686x; 1.1366x over previous
#include <cuda_runtime.h>
#include <cuda_fp16.h>
#include <cstdint>
#include <math.h>

#define B_   8
#define N_   4096
#define K_   32
#define C_   128
#define O_   64
#define NH_  80
#define TN_  4
#define M2_  128            // positions per tile
#define NT_  256            // threads per block
#define NBLK 304            // persistent CTAs (2 per SM x 152)
#define TILES 8192          // B_ * N_ / TN_

// ---- smem layout (bytes) ----
#define SM_W    0           // W hi (80x128 fp16, 20480) + W lo for o>=64 (16x128, 4096)
#define SM_WLO  20480
#define SM_XB   24576       // 2 bufs x 16384: 32c x 128m fp16 (hi 8192 + lo 8192)
#define SM_WFS  57344       // 128 floats
#define SM_OBUF 57856       // 64 x 5 floats = 1280
#define SM_TOTAL 59392

__device__ __forceinline__ uint32_t smem_u32(const void* p) {
    uint32_t a;
    asm("{ .reg .u64 t; cvta.to.shared.u64 t, %1; cvt.u32.u64 %0, t; }" : "=r"(a) : "l"(p));
    return a;
}

#define LDSM_X4(r, a) \
    asm volatile("ldmatrix.sync.aligned.m8n8.x4.shared.b16 {%0,%1,%2,%3}, [%4];" \
        : "=r"((r)[0]), "=r"((r)[1]), "=r"((r)[2]), "=r"((r)[3]) : "r"(a))
#define LDSM_X4_T(r, a) \
    asm volatile("ldmatrix.sync.aligned.m8n8.x4.trans.shared.b16 {%0,%1,%2,%3}, [%4];" \
        : "=r"((r)[0]), "=r"((r)[1]), "=r"((r)[2]), "=r"((r)[3]) : "r"(a))
#define MMA_F16(c, a, b0, b1) \
    asm volatile("mma.sync.aligned.m16n8k16.row.col.f32.f16.f16.f32 " \
        "{%0,%1,%2,%3},{%4,%5,%6,%7},{%8,%9},{%0,%1,%2,%3};" \
        : "+f"((c)[0]), "+f"((c)[1]), "+f"((c)[2]), "+f"((c)[3]) \
        : "r"((a)[0]), "r"((a)[1]), "r"((a)[2]), "r"((a)[3]), "r"(b0), "r"(b1))

// ================= weight prep (same image as R7-R10) =================
__device__ uint4 g_Wimg[1536];   // 24576 B

__global__ void prep_b(const float* __restrict__ wt, const float* __restrict__ wg,
                       const float* __restrict__ wa) {
    int i = blockIdx.x * blockDim.x + threadIdx.x;
    if (i >= NH_ * C_) return;
    int o = i >> 7, c = i & 127;
    float w = (o < 64) ? wt[o * C_ + c]
            : (o < 72) ? wg[(o - 64) * C_ + c]
                       : wa[(o - 72) * C_ + c];
    __half h = __float2half_rn(w);
    unsigned inner = ((((unsigned)(c >> 3) ^ (o & 7)) << 4)) + (c & 7) * 2u;
    __half* base = (__half*)g_Wimg;
    base[((unsigned)o * 256u + inner) >> 1] = h;
    if (o >= 64) {
        __half l = __float2half_rn(w - __half2float(h));
        base[(20480u + (unsigned)(o - 64) * 256u + inner) >> 1] = l;
    }
}

// STS one 32c x 128m chunk (hi+lo fp16 planes), 4 c-rows per thread
__device__ __forceinline__ void sts_chunk(char* base, const float4* stg, int crow, int q) {
    #pragma unroll
    for (int it = 0; it < 4; it++) {
        int c = crow + it * 8;
        float4 v = stg[it];
        __half h0 = __float2half_rn(v.x), h1 = __float2half_rn(v.y);
        __half h2 = __float2half_rn(v.z), h3 = __float2half_rn(v.w);
        __half l0 = __float2half_rn(v.x - __half2float(h0));
        __half l1 = __float2half_rn(v.y - __half2float(h1));
        __half l2 = __float2half_rn(v.z - __half2float(h2));
        __half l3 = __float2half_rn(v.w - __half2float(h3));
        uint2 ph, pl;
        ph.x = (uint32_t)__half_as_ushort(h0) | ((uint32_t)__half_as_ushort(h1) << 16);
        ph.y = (uint32_t)__half_as_ushort(h2) | ((uint32_t)__half_as_ushort(h3) << 16);
        pl.x = (uint32_t)__half_as_ushort(l0) | ((uint32_t)__half_as_ushort(l1) << 16);
        pl.y = (uint32_t)__half_as_ushort(l2) | ((uint32_t)__half_as_ushort(l3) << 16);
        unsigned off = (unsigned)c * 256u + ((((unsigned)(q >> 1)) ^ (c & 7)) << 4) + (q & 1) * 8u;
        *(uint2*)(base + off) = ph;
        *(uint2*)(base + 8192 + off) = pl;
    }
}

// ================= main kernel (persistent) =================
__global__ __launch_bounds__(NT_, 2)
void gsl_mma(const float* __restrict__ x,
             const float* __restrict__ g_trans, const float* __restrict__ b_trans,
             const float* __restrict__ g_gate,  const float* __restrict__ b_gate,
             const float* __restrict__ w_gate2, const float* __restrict__ b_gate2,
             const float* __restrict__ g_attn,  const float* __restrict__ b_attn,
             const float* __restrict__ w_attn2, const float* __restrict__ b_attn2,
             const float* __restrict__ agg_alpha,
             float* __restrict__ out, float* __restrict__ gate_out)
{
    extern __shared__ char smem[];
    const uint32_t sb = smem_u32(smem);
    const int t    = threadIdx.x;
    const int wid  = t >> 5;
    const int lane = t & 31;
    const int mw   = wid & 3;       // n-row within tile
    const int nw   = wid >> 2;      // 0: o 0..47, 1: o 48..79 (+heads)
    const int crow = t >> 5;        // 0..7: c row (mod 8)
    const int q32  = t & 31;        // float4 index within 128m row

    // ---- fragment addressing (tile-invariant) ----
    const int l7   = lane & 7;
    const int koff = (lane >> 3) & 1;
    const int r16  = l7 + ((lane & 16) >> 1);
    uint32_t aBase[2];
    #pragma unroll
    for (int mt = 0; mt < 2; mt++)
        aBase[mt] = sb + SM_XB + r16 * 256 + ((((unsigned)(4 * mw + 2 * mt + koff)) ^ l7) << 4);
    const uint32_t bRowHi = sb + SM_W + r16 * 256;
    const uint32_t bRowLo = sb + SM_WLO + r16 * 256;

    const int qg = lane >> 2;       // 0..7
    const int c4 = lane & 3;        // 0..3
    float* WFs  = (float*)(smem + SM_WFS);
    float* Obuf = (float*)(smem + SM_OBUF);

    // ---- CTA prologue: W image once; first tile chunk0 LDG ----
    int tile = blockIdx.x;
    float4 stg[4];
    {
        uint4 wstg[6];
        #pragma unroll
        for (int i = 0; i < 6; i++) wstg[i] = g_Wimg[t + NT_ * i];
        const int xb0 = (tile >> 10) * (C_ * N_ * K_) + (tile & 1023) * (TN_ * K_);
        #pragma unroll
        for (int it = 0; it < 4; it++)
            stg[it] = *(const float4*)(x + xb0 + (crow + it * 8) * (N_ * K_) + q32 * 4);
        uint4* d = (uint4*)smem;
        #pragma unroll
        for (int i = 0; i < 6; i++) d[t + NT_ * i] = wstg[i];
    }
    const float alpha = 1.0f / (1.0f + __expf(-agg_alpha[0]));

    // ================= persistent tile loop =================
    for (; tile < TILES; tile += NBLK) {
        const int b  = tile >> 10;
        const int nb = (tile & 1023) * TN_;
        const int xbase = b * (C_ * N_ * K_) + nb * K_;

        sts_chunk(smem + SM_XB, stg, crow, q32);
        __syncthreads();

        float acc[2][6][4];
        #pragma unroll
        for (int mt = 0; mt < 2; mt++)
            #pragma unroll
            for (int i = 0; i < 6; i++)
                #pragma unroll
                for (int j = 0; j < 4; j++) acc[mt][i][j] = 0.0f;

        // ---- pipelined mainloop: 4 steps of 32 c ----
        #pragma unroll
        for (int s = 0; s < 4; s++) {
            if (s < 3) {
                #pragma unroll
                for (int it = 0; it < 4; it++) {
                    int c = 32 * (s + 1) + crow + it * 8;
                    stg[it] = *(const float4*)(x + xbase + c * (N_ * K_) + q32 * 4);
                }
            } else {
                // prefetch next tile's chunk 0 (keeps DRAM busy through epilogue)
                const int ntile = tile + NBLK;
                if (ntile < TILES) {
                    const int nxb = (ntile >> 10) * (C_ * N_ * K_) + (ntile & 1023) * (TN_ * K_);
                    #pragma unroll
                    for (int it = 0; it < 4; it++)
                        stg[it] = *(const float4*)(x + nxb + (crow + it * 8) * (N_ * K_) + q32 * 4);
                }
            }
            const uint32_t xb = (uint32_t)(s & 1) * 16384u;
            #pragma unroll
            for (int g = 0; g < 2; g++) {
                const int st16 = 2 * s + g;
                const uint32_t cs = ((((unsigned)(2 * st16 + koff)) ^ l7) << 4);
                uint32_t ah[2][4];
                #pragma unroll
                for (int mt = 0; mt < 2; mt++)
                    LDSM_X4_T(ah[mt], aBase[mt] + xb + g * 4096u);
                if (nw == 0) {
                    #pragma unroll
                    for (int jp = 0; jp < 3; jp++) {
                        uint32_t bh[4];
                        LDSM_X4(bh, bRowHi + jp * 4096 + cs);
                        #pragma unroll
                        for (int mt = 0; mt < 2; mt++) {
                            MMA_F16(acc[mt][2 * jp],     ah[mt], bh[0], bh[1]);
                            MMA_F16(acc[mt][2 * jp + 1], ah[mt], bh[2], bh[3]);
                        }
                    }
                } else {
                    uint32_t al[2][4];
                    #pragma unroll
                    for (int mt = 0; mt < 2; mt++)
                        LDSM_X4_T(al[mt], aBase[mt] + xb + g * 4096u + 8192u);
                    {
                        uint32_t bh[4];
                        LDSM_X4(bh, bRowHi + 3 * 4096 + cs);
                        #pragma unroll
                        for (int mt = 0; mt < 2; mt++) {
                            MMA_F16(acc[mt][0], ah[mt], bh[0], bh[1]);
                            MMA_F16(acc[mt][1], ah[mt], bh[2], bh[3]);
                        }
                    }
                    {
                        uint32_t bh[4], bl[4];
                        LDSM_X4(bh, bRowHi + 4 * 4096 + cs);
                        LDSM_X4(bl, bRowLo + cs);
                        #pragma unroll
                        for (int mt = 0; mt < 2; mt++) {
                            MMA_F16(acc[mt][2], ah[mt], bh[0], bh[1]);
                            MMA_F16(acc[mt][3], ah[mt], bh[2], bh[3]);
                            MMA_F16(acc[mt][2], al[mt], bh[0], bh[1]);
                            MMA_F16(acc[mt][3], al[mt], bh[2], bh[3]);
                            MMA_F16(acc[mt][2], ah[mt], bl[0], bl[1]);
                            MMA_F16(acc[mt][3], ah[mt], bl[2], bl[3]);
                        }
                    }
                }
            }
            if (s < 3) {
                sts_chunk(smem + SM_XB + (((s + 1) & 1) ? 16384 : 0), stg, crow, q32);
                __syncthreads();
            }
        }

        // ================= in-register epilogue (same as R10) =================
        float WFreg[2][2];

        if (nw == 1) {
            float gl[2][2], al[2][2];
            const float bg2 = b_gate2[0], ba2 = b_attn2[0];
            #pragma unroll
            for (int mt = 0; mt < 2; mt++)
                #pragma unroll
                for (int rh = 0; rh < 2; rh++) {
                    float glp = 0.0f, alp = 0.0f;
                    #pragma unroll
                    for (int j = 0; j < 2; j++) {
                        int oc = 2 * c4 + j;
                        float yg = acc[mt][2][2 * rh + j];
                        float v = fmaf(g_gate[oc], yg, b_gate[oc]);
                        v = (v >= 0.0f) ? v : 0.2f * v;
                        glp = fmaf(w_gate2[oc], v, glp);
                        float ya = acc[mt][3][2 * rh + j];
                        float u = fmaf(g_attn[oc], ya, b_attn[oc]);
                        u = (u >= 0.0f) ? u : 0.2f * u;
                        alp = fmaf(w_attn2[oc], u, alp);
                    }
                    glp += __shfl_xor_sync(0xffffffffu, glp, 1);
                    glp += __shfl_xor_sync(0xffffffffu, glp, 2);
                    alp += __shfl_xor_sync(0xffffffffu, alp, 1);
                    alp += __shfl_xor_sync(0xffffffffu, alp, 2);
                    gl[mt][rh] = glp + bg2;
                    al[mt][rh] = alp + ba2;
                }
            float amax = fmaxf(fmaxf(al[0][0], al[0][1]), fmaxf(al[1][0], al[1][1]));
            #pragma unroll
            for (int s = 4; s <= 16; s <<= 1)
                amax = fmaxf(amax, __shfl_xor_sync(0xffffffffu, amax, s));
            float e[2][2];
            float S = 0.0f;
            #pragma unroll
            for (int mt = 0; mt < 2; mt++)
                #pragma unroll
                for (int rh = 0; rh < 2; rh++) {
                    e[mt][rh] = __expf(al[mt][rh] - amax);
                    S += e[mt][rh];
                }
            #pragma unroll
            for (int s = 4; s <= 16; s <<= 1)
                S += __shfl_xor_sync(0xffffffffu, S, s);
            const float invS = 1.0f / S;
            float wm[2][2];
            float Sm = 0.0f;
            #pragma unroll
            for (int mt = 0; mt < 2; mt++)
                #pragma unroll
                for (int rh = 0; rh < 2; rh++) {
                    float w = e[mt][rh] * invS;
                    wm[mt][rh] = (gl[mt][rh] >= 0.0f) ? w : 0.0f;
                    Sm += wm[mt][rh];
                }
            #pragma unroll
            for (int s = 4; s <= 16; s <<= 1)
                Sm += __shfl_xor_sync(0xffffffffu, Sm, s);
            const float rn = 1.0f / (Sm + 1e-6f);
            #pragma unroll
            for (int mt = 0; mt < 2; mt++)
                #pragma unroll
                for (int rh = 0; rh < 2; rh++)
                    WFreg[mt][rh] = wm[mt][rh] * rn;
            if (c4 == 0) {
                const int gbase = b * (N_ * K_) + (nb + mw) * K_;
                #pragma unroll
                for (int mt = 0; mt < 2; mt++)
                    #pragma unroll
                    for (int rh = 0; rh < 2; rh++) {
                        int k = qg + 8 * rh + 16 * mt;
                        WFs[mw * 32 + k] = WFreg[mt][rh];
                        gate_out[gbase + k] = gl[mt][rh];
                    }
            }
        }
        __syncthreads();

        if (nw == 0) {
            #pragma unroll
            for (int mt = 0; mt < 2; mt++)
                #pragma unroll
                for (int rh = 0; rh < 2; rh++)
                    WFreg[mt][rh] = WFs[mw * 32 + qg + 8 * rh + 16 * mt];
        }

        {
            const int ob  = nw * 48;
            const int njj = nw ? 2 : 6;
            for (int jj = 0; jj < njj; jj++) {
                #pragma unroll
                for (int par = 0; par < 2; par++) {
                    const int o = ob + 8 * jj + 2 * c4 + par;
                    const float g  = g_trans[o];
                    const float bb = b_trans[o];
                    float s = 0.0f, mx = -INFINITY;
                    #pragma unroll
                    for (int mt = 0; mt < 2; mt++)
                        #pragma unroll
                        for (int rh = 0; rh < 2; rh++) {
                            float y  = acc[mt][jj][2 * rh + par];
                            float tv = fmaf(g, y, bb);
                            tv = (tv >= 0.0f) ? tv : 0.2f * tv;
                            s  = fmaf(tv, WFreg[mt][rh], s);
                            mx = fmaxf(mx, tv);
                        }
                    #pragma unroll
                    for (int st = 4; st <= 16; st <<= 1) {
                        s += __shfl_xor_sync(0xffffffffu, s, st);
                        mx = fmaxf(mx, __shfl_xor_sync(0xffffffffu, mx, st));
                    }
                    if (qg == 0)
                        Obuf[o * 5 + mw] = alpha * s + (1.0f - alpha) * mx;
                }
            }
        }
        __syncthreads();

        if (t < 64) {
            float4 v;
            v.x = Obuf[t * 5 + 0];
            v.y = Obuf[t * 5 + 1];
            v.z = Obuf[t * 5 + 2];
            v.w = Obuf[t * 5 + 3];
            *(float4*)(out + (b * O_ + t) * N_ + nb) = v;
        }
    }
}

extern "C" void kernel_launch(void* const* d_in, const int* in_sizes, int n_in,
                              void* d_out, int out_size) {
    const float* x        = (const float*)d_in[0];
    const float* w_trans  = (const float*)d_in[1];
    const float* g_trans  = (const float*)d_in[2];
    const float* b_trans  = (const float*)d_in[3];
    const float* w_gate1  = (const float*)d_in[4];
    const float* g_gate   = (const float*)d_in[5];
    const float* b_gate   = (const float*)d_in[6];
    const float* w_gate2  = (const float*)d_in[7];
    const float* b_gate2  = (const float*)d_in[8];
    const float* w_attn1  = (const float*)d_in[9];
    const float* g_attn   = (const float*)d_in[10];
    const float* b_attn   = (const float*)d_in[11];
    const float* w_attn2  = (const float*)d_in[12];
    const float* b_attn2  = (const float*)d_in[13];
    const float* agg_alpha= (const float*)d_in[14];

    float* out      = (float*)d_out;                  // [B,O,N]
    float* gate_out = out + (size_t)B_ * O_ * N_;     // [B,1,N,K]

    cudaFuncSetAttribute(gsl_mma, cudaFuncAttributeMaxDynamicSharedMemorySize, SM_TOTAL);

    prep_b<<<(NH_ * C_ + 255) / 256, 256>>>(w_trans, w_gate1, w_attn1);
    gsl_mma<<<NBLK, NT_, SM_TOTAL>>>(
        x, g_trans, b_trans, g_gate, b_gate, w_gate2, b_gate2,
        g_attn, b_attn, w_attn2, b_attn2, agg_alpha, out, gate_out);
}